// round 5
// baseline (speedup 1.0000x reference)
#include <cuda_runtime.h>
#include <cuda_bf16.h>
#include <cstdint>

// Problem constants
#define NB   8
#define NH   8
#define ND   32
#define NN   1024
#define CDIM 256
#define QKV_M 768
#define SCALE_F 0.17677669529663687f
#define L2E 1.4426950408889634f

// Scratch (device globals — no allocation allowed)
__device__ float g_xt[NB * CDIM * NN];    // tf32-rounded X (natural layout)
__device__ float g_wq[QKV_M * CDIM];      // tf32-rounded w_qkv, k-cols pi-interleaved
__device__ float g_wo[CDIM * CDIM];       // tf32-rounded w_out, k-cols pi-interleaved
__device__ float g_qt[NB * NH * NN * ND]; // scaled+rounded Q, [b][h][n][d] natural
__device__ float g_kt[NB * NH * NN * ND]; // K, [b][h][n][pi(d)]
__device__ float g_vt[NB * NH * NN * ND]; // V transposed, [b][h][d][pi_n(n)]
__device__ float g_ao[NB * CDIM * NN];    // attention out, [b][c][n] natural

// pi within 8-group: [0,4,1,5,2,6,3,7] -> value k at position 2*(k&3)+((k>>2)&1)
__host__ __device__ __forceinline__ int pi8(int k) {
    return (k & ~7) | (((k & 3) << 1) | ((k >> 2) & 1));
}

// ---------------------------------------------------------------------------
// helpers
// ---------------------------------------------------------------------------
__device__ __forceinline__ uint32_t f2tf(float x) {
    uint32_t r;
    asm("cvt.rna.tf32.f32 %0, %1;" : "=r"(r) : "f"(x));
    return r;
}
__device__ __forceinline__ float f2tff(float x) { return __uint_as_float(f2tf(x)); }

__device__ __forceinline__ void mma_tf32(float c[4],
                                         uint32_t a0, uint32_t a1, uint32_t a2, uint32_t a3,
                                         uint32_t b0, uint32_t b1) {
    asm volatile(
        "mma.sync.aligned.m16n8k8.row.col.f32.tf32.tf32.f32 "
        "{%0,%1,%2,%3}, {%4,%5,%6,%7}, {%8,%9}, {%0,%1,%2,%3};\n"
        : "+f"(c[0]), "+f"(c[1]), "+f"(c[2]), "+f"(c[3])
        : "r"(a0), "r"(a1), "r"(a2), "r"(a3), "r"(b0), "r"(b1));
}

__device__ __forceinline__ float ex2f(float x) {
    float r;
    asm("ex2.approx.ftz.f32 %0, %1;" : "=f"(r) : "f"(x));
    return r;
}

__device__ __forceinline__ void cp16(uint32_t dst_smem, const void* src) {
    asm volatile("cp.async.cg.shared.global [%0], [%1], 16;\n" :: "r"(dst_smem), "l"(src));
}
__device__ __forceinline__ void cp_commit() { asm volatile("cp.async.commit_group;\n"); }
__device__ __forceinline__ void cp_wait1() { asm volatile("cp.async.wait_group 1;\n"); }
__device__ __forceinline__ void cp_wait0() { asm volatile("cp.async.wait_group 0;\n"); }

// ---------------------------------------------------------------------------
// Kernel 0: tf32-round X (float4) and weights (scalar, column pi-interleave)
// ---------------------------------------------------------------------------
#define NX4  (NB * CDIM * NN / 4)   // 524288
#define NWQ  (QKV_M * CDIM)         // 196608
#define NWO  (CDIM * CDIM)          // 65536
#define CVT_TOTAL (NX4 + NWQ + NWO) // 786432

__global__ __launch_bounds__(256) void cvt_kernel(const float* __restrict__ x,
                                                  const float* __restrict__ wq,
                                                  const float* __restrict__ wo)
{
    int idx = blockIdx.x * 256 + threadIdx.x;
    if (idx < NX4) {
        float4 v = ((const float4*)x)[idx];
        v.x = f2tff(v.x); v.y = f2tff(v.y); v.z = f2tff(v.z); v.w = f2tff(v.w);
        ((float4*)g_xt)[idx] = v;
    } else if (idx < NX4 + NWQ) {
        int e = idx - NX4;
        int row = e >> 8, c = e & 255;
        g_wq[row * CDIM + pi8(c)] = f2tff(wq[e]);
    } else if (idx < CVT_TOTAL) {
        int e = idx - NX4 - NWQ;
        int row = e >> 8, c = e & 255;
        g_wo[row * CDIM + pi8(c)] = f2tff(wo[e]);
    }
}

// ---------------------------------------------------------------------------
// tf32 MMA GEMM core: C(MxN)=A(MxK)*B(KxN), K=256, tile 64x128x16,
// 3-stage cp.async, 1 sync/iter, STATIC smem 44.5KB. 256 thr = 8 warps
// (2m x 4n), warp tile 32x32. A has pi-interleaved k-cols -> LDS.64 frags.
// ---------------------------------------------------------------------------
#define GBM 64
#define GBN 128
#define GBK 16
#define APAD 24    // 16 + 8; LDS.64 conflict-free: (12g+tig) mod 32 distinct per phase
#define BPAD 136   // 128 + 8
#define A_STG (GBM * APAD)
#define B_STG (GBK * BPAD)
#define KTILES (CDIM / GBK)   // 16

struct GemmAcc { float acc[2][4][4]; };

struct __align__(16) GemmSmem {
    uint32_t As[3][A_STG];
    uint32_t Bs[3][B_STG];
};

__device__ __forceinline__ void gemm_issue(GemmSmem* S, int s,
                                           const float* __restrict__ Ag,
                                           const float* __restrict__ Bg,
                                           int m0, int n0, int k0, int tid)
{
    uint32_t a_base = (uint32_t)__cvta_generic_to_shared(&S->As[s][0]);
    uint32_t b_base = (uint32_t)__cvta_generic_to_shared(&S->Bs[s][0]);
    // A tile 64x16 = 256 f4 chunks, 1 per thread
    {
        int row = tid >> 2, f4 = tid & 3;
        cp16(a_base + (uint32_t)(row * APAD + 4 * f4) * 4,
             Ag + (m0 + row) * CDIM + k0 + 4 * f4);
    }
    // B tile 16x128 = 512 f4 chunks, 2 per thread
    #pragma unroll
    for (int i = 0; i < 2; i++) {
        int slot = i * 256 + tid;
        int row = slot >> 5, f4 = slot & 31;
        cp16(b_base + (uint32_t)(row * BPAD + 4 * f4) * 4,
             Bg + (k0 + row) * NN + n0 + 4 * f4);
    }
    cp_commit();
}

__device__ __forceinline__ void gemm_core(GemmSmem* S,
                                          const float* __restrict__ Ag,
                                          const float* __restrict__ Bg,
                                          int m0, int n0, GemmAcc& R)
{
    const int tid = threadIdx.x;
    const int warp = tid >> 5;
    const int lane = tid & 31;
    const int g = lane >> 2, tig = lane & 3;
    const int wm = (warp >> 2) * 32;   // 2 warps in m
    const int wn = (warp & 3) * 32;    // 4 warps in n

    #pragma unroll
    for (int mt = 0; mt < 2; mt++)
        #pragma unroll
        for (int nt = 0; nt < 4; nt++)
            #pragma unroll
            for (int r = 0; r < 4; r++) R.acc[mt][nt][r] = 0.f;

    gemm_issue(S, 0, Ag, Bg, m0, n0, 0, tid);
    gemm_issue(S, 1, Ag, Bg, m0, n0, GBK, tid);

    #pragma unroll 1
    for (int kt = 0; kt < KTILES; kt++) {
        if (kt == KTILES - 1) cp_wait0(); else cp_wait1();
        __syncthreads();
        if (kt < KTILES - 2)
            gemm_issue(S, (kt + 2) % 3, Ag, Bg, m0, n0, (kt + 2) * GBK, tid);

        const uint32_t* As = S->As[kt % 3];
        const uint32_t* Bs = S->Bs[kt % 3];

        #pragma unroll
        for (int ks = 0; ks < 2; ks++) {
            int kk = ks * 8;
            // A frags: pi-interleaved -> (a0,a2) and (a1,a3) as LDS.64
            uint32_t af[2][4];
            #pragma unroll
            for (int mt = 0; mt < 2; mt++) {
                int r = wm + 16 * mt;
                uint2 lo = *(const uint2*)&As[(r + g) * APAD + kk + 2 * tig];
                uint2 hi = *(const uint2*)&As[(r + g + 8) * APAD + kk + 2 * tig];
                af[mt][0] = lo.x; af[mt][2] = lo.y;
                af[mt][1] = hi.x; af[mt][3] = hi.y;
            }
            #pragma unroll
            for (int nt = 0; nt < 4; nt++) {
                uint32_t b0 = Bs[(kk + tig) * BPAD + wn + 8 * nt + g];
                uint32_t b1 = Bs[(kk + tig + 4) * BPAD + wn + 8 * nt + g];
                mma_tf32(R.acc[0][nt], af[0][0], af[0][1], af[0][2], af[0][3], b0, b1);
                mma_tf32(R.acc[1][nt], af[1][0], af[1][1], af[1][2], af[1][3], b0, b1);
            }
        }
    }
}

// Kernel 1: QKV projection -> head-major scratch with attention layouts.
__global__ __launch_bounds__(256) void qkv_gemm_kernel()
{
    __shared__ GemmSmem S;
    const int b = blockIdx.z;
    const int m0 = blockIdx.y * GBM;
    const int n0 = blockIdx.x * GBN;

    GemmAcc R;
    gemm_core(&S, g_wq, g_xt + (size_t)b * CDIM * NN, m0, n0, R);

    const int tid = threadIdx.x;
    const int warp = tid >> 5, lane = tid & 31;
    const int g = lane >> 2, tig = lane & 3;
    const int wm = (warp >> 2) * 32, wn = (warp & 3) * 32;

    #pragma unroll
    for (int mt = 0; mt < 2; mt++) {
        #pragma unroll
        for (int half = 0; half < 2; half++) {
            int o = m0 + wm + 16 * mt + g + 8 * half;
            int grp = o >> 8;
            int hh = (o >> 5) & 7;
            int dd = o & 31;
            size_t bh = (size_t)(b * NH + hh);
            #pragma unroll
            for (int nt = 0; nt < 4; nt++) {
                int n = n0 + wn + 8 * nt + 2 * tig;
                float v0 = R.acc[mt][nt][2 * half];
                float v1 = R.acc[mt][nt][2 * half + 1];
                if (grp == 0) {
                    float* dst = g_qt + bh * NN * ND + dd;
                    dst[(size_t)n * ND]       = f2tff(v0 * SCALE_F);
                    dst[(size_t)(n + 1) * ND] = f2tff(v1 * SCALE_F);
                } else if (grp == 1) {
                    float* dst = g_kt + bh * NN * ND + pi8(dd);
                    dst[(size_t)n * ND]       = f2tff(v0);
                    dst[(size_t)(n + 1) * ND] = f2tff(v1);
                } else {
                    float* dst = g_vt + (bh * ND + dd) * NN;
                    dst[pi8(n)]     = f2tff(v0);
                    dst[pi8(n + 1)] = f2tff(v1);
                }
            }
        }
    }
}

// Kernel 3: output projection + bias.
__global__ __launch_bounds__(256) void out_gemm_kernel(const float* __restrict__ bias,
                                                       float* __restrict__ Y)
{
    __shared__ GemmSmem S;
    const int b = blockIdx.z;
    const int m0 = blockIdx.y * GBM;
    const int n0 = blockIdx.x * GBN;

    GemmAcc R;
    gemm_core(&S, g_wo, g_ao + (size_t)b * CDIM * NN, m0, n0, R);

    const int tid = threadIdx.x;
    const int warp = tid >> 5, lane = tid & 31;
    const int g = lane >> 2, tig = lane & 3;
    const int wm = (warp >> 2) * 32, wn = (warp & 3) * 32;

    #pragma unroll
    for (int mt = 0; mt < 2; mt++) {
        #pragma unroll
        for (int half = 0; half < 2; half++) {
            int o = m0 + wm + 16 * mt + g + 8 * half;
            float bv = bias[o];
            float* yrow = Y + ((size_t)b * CDIM + o) * NN;
            #pragma unroll
            for (int nt = 0; nt < 4; nt++) {
                int n = n0 + wn + 8 * nt + 2 * tig;
                yrow[n]     = R.acc[mt][nt][2 * half]     + bv;
                yrow[n + 1] = R.acc[mt][nt][2 * half + 1] + bv;
            }
        }
    }
}

// ---------------------------------------------------------------------------
// Kernel 2: flash attention. 128 threads (4 warps), Br=64 (16/warp), Bc=32.
// 3-stage cp.async K/V, 1 sync/tile. K: [n][pi(d)] -> S B-frags via LDS.64.
// V: [d][pi(n)] transposed -> PV B-frags via LDS.64. Static smem 46.1KB.
// ---------------------------------------------------------------------------
#define QPAD 36
#define KPAD 36
#define VPAD 36
#define PPAD 36
#define BC   32
#define NTILES (NN / BC)   // 32
#define K_STG (BC * KPAD)
#define V_STG (BC * VPAD)

struct __align__(16) AttnSmem {
    uint32_t Qs[64 * QPAD];
    uint32_t Ks[3][K_STG];
    uint32_t Vs[3][V_STG];
    uint32_t Ps[4][16 * PPAD];
};

__device__ __forceinline__ void attn_issue(AttnSmem* S, int s,
                                           const float* __restrict__ Kg,
                                           const float* __restrict__ Vg,
                                           int j0, int tid)
{
    uint32_t k_base = (uint32_t)__cvta_generic_to_shared(&S->Ks[s][0]);
    uint32_t v_base = (uint32_t)__cvta_generic_to_shared(&S->Vs[s][0]);
    // K tile: 32 tokens x 32 d (pi-interleaved in gmem) = 256 chunks
    // V tile: 32 d-rows x 32 j (pi-interleaved in gmem)  = 256 chunks
    #pragma unroll
    for (int i = 0; i < 2; i++) {
        int slot = i * 128 + tid;
        int row = slot >> 3, f4 = slot & 7;
        cp16(k_base + (uint32_t)(row * KPAD + 4 * f4) * 4,
             Kg + (size_t)(j0 + row) * ND + 4 * f4);
        cp16(v_base + (uint32_t)(row * VPAD + 4 * f4) * 4,
             Vg + (size_t)row * NN + j0 + 4 * f4);
    }
    cp_commit();
}

__global__ __launch_bounds__(128) void attn_kernel()
{
    __shared__ AttnSmem S;

    const int b = blockIdx.z;
    const int h = blockIdx.y;
    const int q0 = blockIdx.x * 64;

    const int tid = threadIdx.x;
    const int warp = tid >> 5, lane = tid & 31;
    const int g = lane >> 2, tig = lane & 3;

    const size_t headBase = (size_t)(b * NH + h) * NN * ND;
    const float* Qg = g_qt + headBase;
    const float* Kg = g_kt + headBase;
    const float* Vg = g_vt + headBase;   // [d][pi(n)]

    attn_issue(&S, 0, Kg, Vg, 0, tid);
    attn_issue(&S, 1, Kg, Vg, BC, tid);

    // Load Q tile (64x32), natural d order
    #pragma unroll
    for (int i = 0; i < 4; i++) {
        int slot = i * 128 + tid;
        int row = slot >> 3, f4 = slot & 7;
        float4 qv = *(const float4*)&Qg[(size_t)(q0 + row) * ND + 4 * f4];
        uint4 u;
        u.x = __float_as_uint(qv.x); u.y = __float_as_uint(qv.y);
        u.z = __float_as_uint(qv.z); u.w = __float_as_uint(qv.w);
        *(uint4*)&S.Qs[row * QPAD + 4 * f4] = u;
    }
    __syncthreads();

    // Hoist Q frags (k-index natural)
    uint32_t qf[4][4];
    #pragma unroll
    for (int ks = 0; ks < 4; ks++) {
        int kk = 8 * ks;
        int r = 16 * warp;
        qf[ks][0] = S.Qs[(r + g) * QPAD + kk + tig];
        qf[ks][1] = S.Qs[(r + g + 8) * QPAD + kk + tig];
        qf[ks][2] = S.Qs[(r + g) * QPAD + kk + tig + 4];
        qf[ks][3] = S.Qs[(r + g + 8) * QPAD + kk + tig + 4];
    }

    float oacc[4][4];
    #pragma unroll
    for (int dt = 0; dt < 4; dt++)
        #pragma unroll
        for (int r = 0; r < 4; r++) oacc[dt][r] = 0.f;
    float m0 = -1e30f, m1 = -1e30f, l0 = 0.f, l1 = 0.f;

    uint32_t* Pw = S.Ps[warp];

    #pragma unroll 1
    for (int t = 0; t < NTILES; t++) {
        if (t == NTILES - 1) cp_wait0(); else cp_wait1();
        __syncthreads();
        if (t < NTILES - 2)
            attn_issue(&S, (t + 2) % 3, Kg, Vg, (t + 2) * BC, tid);

        const uint32_t* Ks = S.Ks[t % 3];
        const uint32_t* Vs = S.Vs[t % 3];

        // S = Q K^T : [16 x 32] per warp. K B-frags via LDS.64 (pi-interleave).
        float sacc[4][4];
        #pragma unroll
        for (int nt = 0; nt < 4; nt++)
            #pragma unroll
            for (int r = 0; r < 4; r++) sacc[nt][r] = 0.f;
        #pragma unroll
        for (int ks = 0; ks < 4; ks++) {
            int kk = 8 * ks;
            #pragma unroll
            for (int nt = 0; nt < 4; nt++) {
                uint2 bb = *(const uint2*)&Ks[(8 * nt + g) * KPAD + kk + 2 * tig];
                mma_tf32(sacc[nt], qf[ks][0], qf[ks][1], qf[ks][2], qf[ks][3], bb.x, bb.y);
            }
        }

        // Online softmax
        float mx0 = -1e30f, mx1 = -1e30f;
        #pragma unroll
        for (int nt = 0; nt < 4; nt++) {
            mx0 = fmaxf(mx0, fmaxf(sacc[nt][0], sacc[nt][1]));
            mx1 = fmaxf(mx1, fmaxf(sacc[nt][2], sacc[nt][3]));
        }
        mx0 = fmaxf(mx0, __shfl_xor_sync(0xffffffff, mx0, 1));
        mx0 = fmaxf(mx0, __shfl_xor_sync(0xffffffff, mx0, 2));
        mx1 = fmaxf(mx1, __shfl_xor_sync(0xffffffff, mx1, 1));
        mx1 = fmaxf(mx1, __shfl_xor_sync(0xffffffff, mx1, 2));

        float mn0 = fmaxf(m0, mx0);
        float mn1 = fmaxf(m1, mx1);
        float sc0 = ex2f((m0 - mn0) * L2E);
        float sc1 = ex2f((m1 - mn1) * L2E);
        m0 = mn0; m1 = mn1;
        float mb0 = mn0 * L2E, mb1 = mn1 * L2E;

        float sum0 = 0.f, sum1 = 0.f;
        float p[4][4];
        #pragma unroll
        for (int nt = 0; nt < 4; nt++) {
            p[nt][0] = ex2f(fmaf(sacc[nt][0], L2E, -mb0));
            p[nt][1] = ex2f(fmaf(sacc[nt][1], L2E, -mb0));
            p[nt][2] = ex2f(fmaf(sacc[nt][2], L2E, -mb1));
            p[nt][3] = ex2f(fmaf(sacc[nt][3], L2E, -mb1));
            sum0 += p[nt][0] + p[nt][1];
            sum1 += p[nt][2] + p[nt][3];
        }
        sum0 += __shfl_xor_sync(0xffffffff, sum0, 1);
        sum0 += __shfl_xor_sync(0xffffffff, sum0, 2);
        sum1 += __shfl_xor_sync(0xffffffff, sum1, 1);
        sum1 += __shfl_xor_sync(0xffffffff, sum1, 2);
        l0 = l0 * sc0 + sum0;
        l1 = l1 * sc1 + sum1;

        #pragma unroll
        for (int dt = 0; dt < 4; dt++) {
            oacc[dt][0] *= sc0; oacc[dt][1] *= sc0;
            oacc[dt][2] *= sc1; oacc[dt][3] *= sc1;
        }

        // Store P (tf32) to warp-private smem, natural column order
        #pragma unroll
        for (int nt = 0; nt < 4; nt++) {
            uint2 u0, u1;
            u0.x = f2tf(p[nt][0]); u0.y = f2tf(p[nt][1]);
            u1.x = f2tf(p[nt][2]); u1.y = f2tf(p[nt][3]);
            *(uint2*)&Pw[g * PPAD + 8 * nt + 2 * tig]       = u0;
            *(uint2*)&Pw[(g + 8) * PPAD + 8 * nt + 2 * tig] = u1;
        }
        __syncwarp();

        // O += P V : A = P [16x32] (natural j), B = Vt (pi-interleaved j) LDS.64
        #pragma unroll
        for (int ks2 = 0; ks2 < 4; ks2++) {
            int kk = 8 * ks2;
            uint32_t a0 = Pw[g * PPAD + kk + tig];
            uint32_t a1 = Pw[(g + 8) * PPAD + kk + tig];
            uint32_t a2 = Pw[g * PPAD + kk + tig + 4];
            uint32_t a3 = Pw[(g + 8) * PPAD + kk + tig + 4];
            #pragma unroll
            for (int dt = 0; dt < 4; dt++) {
                uint2 bb = *(const uint2*)&Vs[(8 * dt + g) * VPAD + kk + 2 * tig];
                mma_tf32(oacc[dt], a0, a1, a2, a3, bb.x, bb.y);
            }
        }
        __syncwarp();
    }

    // Epilogue: normalize, round, write [b][c][n]
    float inv0 = 1.0f / l0;
    float inv1 = 1.0f / l1;
    int n_row0 = q0 + 16 * warp + g;
    float* aoB = g_ao + ((size_t)b * CDIM + h * ND) * NN;
    #pragma unroll
    for (int dt = 0; dt < 4; dt++) {
        int d = 8 * dt + 2 * tig;
        aoB[(size_t)d * NN + n_row0]           = f2tff(oacc[dt][0] * inv0);
        aoB[(size_t)(d + 1) * NN + n_row0]     = f2tff(oacc[dt][1] * inv0);
        aoB[(size_t)d * NN + n_row0 + 8]       = f2tff(oacc[dt][2] * inv1);
        aoB[(size_t)(d + 1) * NN + n_row0 + 8] = f2tff(oacc[dt][3] * inv1);
    }
}

// ---------------------------------------------------------------------------
extern "C" void kernel_launch(void* const* d_in, const int* in_sizes, int n_in,
                              void* d_out, int out_size)
{
    const float* x     = (const float*)d_in[0];
    const float* w_qkv = (const float*)d_in[1];
    const float* w_out = (const float*)d_in[2];
    const float* b_out = (const float*)d_in[3];
    float* y = (float*)d_out;

    cvt_kernel<<<CVT_TOTAL / 256, 256>>>(x, w_qkv, w_out);
    qkv_gemm_kernel<<<dim3(NN / GBN, QKV_M / GBM, NB), 256>>>();
    attn_kernel<<<dim3(NN / 64, NH, NB), 128>>>();
    out_gemm_kernel<<<dim3(NN / GBN, CDIM / GBM, NB), 256>>>(b_out, y);
}

// round 8
// speedup vs baseline: 1.1839x; 1.1839x over previous
#include <cuda_runtime.h>
#include <cuda_bf16.h>
#include <cstdint>

// Problem constants
#define NB   8
#define NH   8
#define ND   32
#define NN   1024
#define CDIM 256
#define QKV_M 768
#define SCALE_F 0.17677669529663687f
#define L2E 1.4426950408889634f

// Scratch (device globals — no allocation allowed)
__device__ float g_qt[NB * NH * NN * ND]; // tf32 Q (scaled), [b][h][n][pi8(d)]
__device__ float g_kt[NB * NH * NN * ND]; // tf32 K, [b][h][n][pi8(d)]
__device__ float g_vt[NB * NH * NN * ND]; // tf32 V, [b][h][d][pi8(n)] (transposed)
__device__ float g_ao[NB * CDIM * NN];    // attention out, [b][c][n]

// pi within 8-group: k -> 2*(k&3) + ((k>>2)&1)  (pairs (t, t+4) become adjacent)
__host__ __device__ __forceinline__ int pi8(int k) {
    return (k & ~7) | (((k & 3) << 1) | ((k >> 2) & 1));
}

// ---------------------------------------------------------------------------
// helpers
// ---------------------------------------------------------------------------
__device__ __forceinline__ uint32_t f2tf(float x) {
    uint32_t r;
    asm("cvt.rna.tf32.f32 %0, %1;" : "=r"(r) : "f"(x));
    return r;
}
__device__ __forceinline__ float f2tff(float x) { return __uint_as_float(f2tf(x)); }

__device__ __forceinline__ void mma_tf32(float c[4],
                                         uint32_t a0, uint32_t a1, uint32_t a2, uint32_t a3,
                                         uint32_t b0, uint32_t b1) {
    asm volatile(
        "mma.sync.aligned.m16n8k8.row.col.f32.tf32.tf32.f32 "
        "{%0,%1,%2,%3}, {%4,%5,%6,%7}, {%8,%9}, {%0,%1,%2,%3};\n"
        : "+f"(c[0]), "+f"(c[1]), "+f"(c[2]), "+f"(c[3])
        : "r"(a0), "r"(a1), "r"(a2), "r"(a3), "r"(b0), "r"(b1));
}

__device__ __forceinline__ float ex2f(float x) {
    float r;
    asm("ex2.approx.ftz.f32 %0, %1;" : "=f"(r) : "f"(x));
    return r;
}

// ---------------------------------------------------------------------------
// tf32 MMA GEMM (exact R2 structure): C(MxN)=A(MxK)*B(KxN), K=256,
// tile 128x128x32, inline cvt, static smem. 256 threads = 8 warps (4m x 2n).
// ---------------------------------------------------------------------------
#define GBM 128
#define GBN 128
#define GBK 32
#define APAD 36
#define BPAD 136

struct GemmAcc { float acc[2][8][4]; };

__device__ __forceinline__ void gemm_core(uint32_t (*As)[APAD], uint32_t (*Bs)[BPAD],
                                          const float* __restrict__ Ag,
                                          const float* __restrict__ Bg,
                                          int m0, int n0, GemmAcc& R)
{
    const int tid = threadIdx.x;
    const int warp = tid >> 5;
    const int lane = tid & 31;
    const int g = lane >> 2, tig = lane & 3;
    const int wm = (warp >> 1) * 32;
    const int wn = (warp & 1) * 64;

    #pragma unroll
    for (int mt = 0; mt < 2; mt++)
        #pragma unroll
        for (int nt = 0; nt < 8; nt++)
            #pragma unroll
            for (int r = 0; r < 4; r++) R.acc[mt][nt][r] = 0.f;

    for (int k0 = 0; k0 < CDIM; k0 += GBK) {
        #pragma unroll
        for (int i = 0; i < 4; i++) {
            int slot = i * 256 + tid;
            int row = slot >> 3, f4 = slot & 7;
            float4 a = *(const float4*)&Ag[(m0 + row) * CDIM + k0 + 4 * f4];
            uint4 u;
            u.x = f2tf(a.x); u.y = f2tf(a.y); u.z = f2tf(a.z); u.w = f2tf(a.w);
            *(uint4*)&As[row][4 * f4] = u;
        }
        #pragma unroll
        for (int i = 0; i < 4; i++) {
            int slot = i * 256 + tid;
            int row = slot >> 5, f4 = slot & 31;
            float4 b = *(const float4*)&Bg[(k0 + row) * NN + n0 + 4 * f4];
            uint4 u;
            u.x = f2tf(b.x); u.y = f2tf(b.y); u.z = f2tf(b.z); u.w = f2tf(b.w);
            *(uint4*)&Bs[row][4 * f4] = u;
        }
        __syncthreads();

        #pragma unroll
        for (int ks = 0; ks < 4; ks++) {
            int kk = ks * 8;
            uint32_t af[2][4];
            #pragma unroll
            for (int mt = 0; mt < 2; mt++) {
                int r = wm + 16 * mt;
                af[mt][0] = As[r + g][kk + tig];
                af[mt][1] = As[r + g + 8][kk + tig];
                af[mt][2] = As[r + g][kk + tig + 4];
                af[mt][3] = As[r + g + 8][kk + tig + 4];
            }
            #pragma unroll
            for (int nt = 0; nt < 8; nt++) {
                uint32_t b0 = Bs[kk + tig][wn + 8 * nt + g];
                uint32_t b1 = Bs[kk + tig + 4][wn + 8 * nt + g];
                mma_tf32(R.acc[0][nt], af[0][0], af[0][1], af[0][2], af[0][3], b0, b1);
                mma_tf32(R.acc[1][nt], af[1][0], af[1][1], af[1][2], af[1][3], b0, b1);
            }
        }
        __syncthreads();
    }
}

// Kernel 1: QKV projection; epilogue writes attention-ready layouts (tf32-rounded).
__global__ __launch_bounds__(256) void qkv_gemm_kernel(
    const float* __restrict__ W,   // [768, 256]
    const float* __restrict__ X)   // [B, 256, 1024]
{
    __shared__ uint32_t As[GBM][APAD];
    __shared__ uint32_t Bs[GBK][BPAD];
    const int b = blockIdx.z;
    const int m0 = blockIdx.y * GBM;
    const int n0 = blockIdx.x * GBN;

    GemmAcc R;
    gemm_core(As, Bs, W, X + (size_t)b * CDIM * NN, m0, n0, R);

    const int tid = threadIdx.x;
    const int warp = tid >> 5, lane = tid & 31;
    const int g = lane >> 2, tig = lane & 3;
    const int wm = (warp >> 1) * 32, wn = (warp & 1) * 64;

    #pragma unroll
    for (int mt = 0; mt < 2; mt++) {
        #pragma unroll
        for (int half = 0; half < 2; half++) {
            int o = m0 + wm + 16 * mt + g + 8 * half;
            int grp = o >> 8;
            int hh = (o >> 5) & 7;
            int dd = o & 31;
            size_t bh = (size_t)(b * NH + hh);
            #pragma unroll
            for (int nt = 0; nt < 8; nt++) {
                int n = n0 + wn + 8 * nt + 2 * tig;
                float v0 = R.acc[mt][nt][2 * half];
                float v1 = R.acc[mt][nt][2 * half + 1];
                if (grp == 0) {
                    float* dst = g_qt + bh * NN * ND + pi8(dd);
                    dst[(size_t)n * ND]       = f2tff(v0 * SCALE_F);
                    dst[(size_t)(n + 1) * ND] = f2tff(v1 * SCALE_F);
                } else if (grp == 1) {
                    float* dst = g_kt + bh * NN * ND + pi8(dd);
                    dst[(size_t)n * ND]       = f2tff(v0);
                    dst[(size_t)(n + 1) * ND] = f2tff(v1);
                } else {
                    float* dst = g_vt + (bh * ND + dd) * NN;
                    dst[pi8(n)]     = f2tff(v0);
                    dst[pi8(n + 1)] = f2tff(v1);
                }
            }
        }
    }
}

// Kernel 3: output projection + bias (exact R2).
__global__ __launch_bounds__(256) void out_gemm_kernel(
    const float* __restrict__ W,     // [256, 256]
    const float* __restrict__ bias,  // [256]
    float* __restrict__ Y)           // [B, 256, 1024]
{
    __shared__ uint32_t As[GBM][APAD];
    __shared__ uint32_t Bs[GBK][BPAD];
    const int b = blockIdx.z;
    const int m0 = blockIdx.y * GBM;
    const int n0 = blockIdx.x * GBN;

    GemmAcc R;
    gemm_core(As, Bs, W, g_ao + (size_t)b * CDIM * NN, m0, n0, R);

    const int tid = threadIdx.x;
    const int warp = tid >> 5, lane = tid & 31;
    const int g = lane >> 2, tig = lane & 3;
    const int wm = (warp >> 1) * 32, wn = (warp & 1) * 64;

    #pragma unroll
    for (int mt = 0; mt < 2; mt++) {
        #pragma unroll
        for (int half = 0; half < 2; half++) {
            int o = m0 + wm + 16 * mt + g + 8 * half;
            float bv = bias[o];
            float* yrow = Y + ((size_t)b * CDIM + o) * NN;
            #pragma unroll
            for (int nt = 0; nt < 8; nt++) {
                int n = n0 + wn + 8 * nt + 2 * tig;
                yrow[n]     = R.acc[mt][nt][2 * half]     + bv;
                yrow[n + 1] = R.acc[mt][nt][2 * half + 1] + bv;
            }
        }
    }
}

// ---------------------------------------------------------------------------
// Kernel 2: flash attention, no-max softmax, P via per-warp smem (validated
// R2 pattern). 128 threads (4 warps), Br=64 (16 rows/warp), Bc=64, d=32.
// Q/K interleaved d in gmem; V transposed+interleaved j in gmem -> all smem
// stores verbatim STS.128; Q/K/V MMA frag pairs are conflict-free LDS.64.
// Static smem 46KB.
// ---------------------------------------------------------------------------
#define QPAD 40
#define KPAD 40
#define VPADT 72
#define PPAD 68
#define BC   64
#define NTILES (NN / BC)   // 16

__global__ __launch_bounds__(128) void attn_kernel()
{
    __shared__ uint32_t Qs[64][QPAD];    // 10.0 KB
    __shared__ uint32_t Ks[BC][KPAD];    // 10.0 KB
    __shared__ uint32_t Vs[ND][VPADT];   //  9.0 KB
    __shared__ uint32_t Ps[4][16 * PPAD];// 17.0 KB

    const int b = blockIdx.z;
    const int h = blockIdx.y;
    const int q0 = blockIdx.x * 64;

    const int tid = threadIdx.x;
    const int warp = tid >> 5, lane = tid & 31;
    const int g = lane >> 2, tig = lane & 3;

    const size_t headBase = (size_t)(b * NH + h) * NN * ND;
    const float* Qg = g_qt + headBase;   // [n][pi(d)]
    const float* Kg = g_kt + headBase;   // [n][pi(d)]
    const float* Vg = g_vt + headBase;   // [d][pi(n)]

    // Load Q tile (64x32) verbatim (already tf32 + interleaved): 512 uint4
    #pragma unroll
    for (int i = 0; i < 4; i++) {
        int slot = i * 128 + tid;
        int row = slot >> 3, f4 = slot & 7;
        *(uint4*)&Qs[row][4 * f4] =
            *(const uint4*)&Qg[(size_t)(q0 + row) * ND + 4 * f4];
    }
    __syncthreads();

    // Hoist Q frags: warp owns rows [16*warp, 16*warp+16). LDS.64 pairs.
    uint32_t qf[4][4];
    #pragma unroll
    for (int ks = 0; ks < 4; ks++) {
        int kk = 8 * ks;
        int r = 16 * warp;
        uint2 lo = *(const uint2*)&Qs[r + g][kk + 2 * tig];
        uint2 hi = *(const uint2*)&Qs[r + g + 8][kk + 2 * tig];
        qf[ks][0] = lo.x; qf[ks][2] = lo.y;
        qf[ks][1] = hi.x; qf[ks][3] = hi.y;
    }

    float oacc[4][4];
    #pragma unroll
    for (int dt = 0; dt < 4; dt++)
        #pragma unroll
        for (int r = 0; r < 4; r++) oacc[dt][r] = 0.f;
    float sum0 = 0.f, sum1 = 0.f;   // un-normalized row sums (no max needed)

    uint32_t* Pw = Ps[warp];

    for (int t = 0; t < NTILES; t++) {
        int j0 = t * BC;
        __syncthreads();  // prior iter done reading Ks/Vs
        // K tile 64x32 (512 uint4) + V tile 32x64 (512 uint4), verbatim.
        #pragma unroll
        for (int i = 0; i < 4; i++) {
            int slot = i * 128 + tid;
            int krow = slot >> 3, kf4 = slot & 7;
            *(uint4*)&Ks[krow][4 * kf4] =
                *(const uint4*)&Kg[(size_t)(j0 + krow) * ND + 4 * kf4];
            int vrow = slot >> 4, vf4 = slot & 15;
            *(uint4*)&Vs[vrow][4 * vf4] =
                *(const uint4*)&Vg[(size_t)vrow * NN + j0 + 4 * vf4];
        }
        __syncthreads();

        // S = Q K^T : [16 x 64] per warp; B-frags as LDS.64
        float sacc[8][4];
        #pragma unroll
        for (int nt = 0; nt < 8; nt++)
            #pragma unroll
            for (int r = 0; r < 4; r++) sacc[nt][r] = 0.f;
        #pragma unroll
        for (int ks = 0; ks < 4; ks++) {
            int kk = 8 * ks;
            #pragma unroll
            for (int nt = 0; nt < 8; nt++) {
                uint2 bb = *(const uint2*)&Ks[8 * nt + g][kk + 2 * tig];
                mma_tf32(sacc[nt], qf[ks][0], qf[ks][1], qf[ks][2], qf[ks][3], bb.x, bb.y);
            }
        }

        // p = exp2(s * log2e); accumulate row sums; store P (tf32) to smem
        #pragma unroll
        for (int nt = 0; nt < 8; nt++) {
            float p0 = ex2f(sacc[nt][0] * L2E);
            float p1 = ex2f(sacc[nt][1] * L2E);
            float p2 = ex2f(sacc[nt][2] * L2E);
            float p3 = ex2f(sacc[nt][3] * L2E);
            sum0 += p0 + p1;
            sum1 += p2 + p3;
            uint2 u0, u1;
            u0.x = f2tf(p0); u0.y = f2tf(p1);
            u1.x = f2tf(p2); u1.y = f2tf(p3);
            *(uint2*)&Pw[g * PPAD + 8 * nt + 2 * tig]       = u0;
            *(uint2*)&Pw[(g + 8) * PPAD + 8 * nt + 2 * tig] = u1;
        }
        __syncwarp();

        // O += P V : A = P [16x64], B = V^T tile [64x32] (LDS.64 B-frags)
        #pragma unroll
        for (int ks2 = 0; ks2 < 8; ks2++) {
            int kk = 8 * ks2;
            uint32_t a0 = Pw[g * PPAD + kk + tig];
            uint32_t a1 = Pw[(g + 8) * PPAD + kk + tig];
            uint32_t a2 = Pw[g * PPAD + kk + tig + 4];
            uint32_t a3 = Pw[(g + 8) * PPAD + kk + tig + 4];
            #pragma unroll
            for (int dt = 0; dt < 4; dt++) {
                uint2 bb = *(const uint2*)&Vs[8 * dt + g][kk + 2 * tig];
                mma_tf32(oacc[dt], a0, a1, a2, a3, bb.x, bb.y);
            }
        }
        __syncwarp();
    }

    // Final row-sum reduction across the 4-thread group, normalize, store.
    sum0 += __shfl_xor_sync(0xffffffff, sum0, 1);
    sum0 += __shfl_xor_sync(0xffffffff, sum0, 2);
    sum1 += __shfl_xor_sync(0xffffffff, sum1, 1);
    sum1 += __shfl_xor_sync(0xffffffff, sum1, 2);
    float inv0 = 1.0f / sum0;
    float inv1 = 1.0f / sum1;

    int n_row0 = q0 + 16 * warp + g;
    float* aoB = g_ao + ((size_t)b * CDIM + h * ND) * NN;
    #pragma unroll
    for (int dt = 0; dt < 4; dt++) {
        int d = 8 * dt + 2 * tig;
        aoB[(size_t)d * NN + n_row0]           = oacc[dt][0] * inv0;
        aoB[(size_t)(d + 1) * NN + n_row0]     = oacc[dt][1] * inv0;
        aoB[(size_t)d * NN + n_row0 + 8]       = oacc[dt][2] * inv1;
        aoB[(size_t)(d + 1) * NN + n_row0 + 8] = oacc[dt][3] * inv1;
    }
}

// ---------------------------------------------------------------------------
extern "C" void kernel_launch(void* const* d_in, const int* in_sizes, int n_in,
                              void* d_out, int out_size)
{
    const float* x     = (const float*)d_in[0];
    const float* w_qkv = (const float*)d_in[1];
    const float* w_out = (const float*)d_in[2];
    const float* b_out = (const float*)d_in[3];
    float* y = (float*)d_out;

    qkv_gemm_kernel<<<dim3(NN / GBN, QKV_M / GBM, NB), 256>>>(w_qkv, x);
    attn_kernel<<<dim3(NN / 64, NH, NB), 128>>>();
    out_gemm_kernel<<<dim3(NN / GBN, CDIM / GBM, NB), 256>>>(w_out, b_out, y);
}

// round 9
// speedup vs baseline: 2.2905x; 1.9347x over previous
#include <cuda_runtime.h>
#include <cuda_fp16.h>
#include <cstdint>

// Problem constants
#define NB   8
#define NH   8
#define ND   32
#define NN   1024
#define CDIM 256
#define QKV_M 768
#define SCALE_F 0.17677669529663687f
#define L2E 1.4426950408889634f

// Scratch (device globals — no allocation allowed)
__device__ __half g_qh[NB * NH * ND * NN]; // fp16 Q (scaled), [b][h][d][n]
__device__ __half g_kh[NB * NH * ND * NN]; // fp16 K, [b][h][d][n]
__device__ __half g_vh[NB * NH * ND * NN]; // fp16 V, [b][h][d][n]
__device__ float  g_ao[NB * CDIM * NN];    // attention out, fp32 [b][c][n]

// ---------------------------------------------------------------------------
// helpers
// ---------------------------------------------------------------------------
__device__ __forceinline__ uint32_t f2h2(float lo, float hi) {
    uint32_t r;
    asm("cvt.rn.f16x2.f32 %0, %1, %2;" : "=r"(r) : "f"(hi), "f"(lo));
    return r;
}

__device__ __forceinline__ float ex2f(float x) {
    float r;
    asm("ex2.approx.ftz.f32 %0, %1;" : "=f"(r) : "f"(x));
    return r;
}

__device__ __forceinline__ void mma_f16(float c[4],
                                        uint32_t a0, uint32_t a1, uint32_t a2, uint32_t a3,
                                        uint32_t b0, uint32_t b1) {
    asm volatile(
        "mma.sync.aligned.m16n8k16.row.col.f32.f16.f16.f32 "
        "{%0,%1,%2,%3}, {%4,%5,%6,%7}, {%8,%9}, {%0,%1,%2,%3};\n"
        : "+f"(c[0]), "+f"(c[1]), "+f"(c[2]), "+f"(c[3])
        : "r"(a0), "r"(a1), "r"(a2), "r"(a3), "r"(b0), "r"(b1));
}

__device__ __forceinline__ void ldsm4(uint32_t& r0, uint32_t& r1, uint32_t& r2, uint32_t& r3,
                                      uint32_t addr) {
    asm volatile("ldmatrix.sync.aligned.m8n8.x4.shared.b16 {%0,%1,%2,%3}, [%4];"
                 : "=r"(r0), "=r"(r1), "=r"(r2), "=r"(r3) : "r"(addr));
}

__device__ __forceinline__ void ldsm4t(uint32_t& r0, uint32_t& r1, uint32_t& r2, uint32_t& r3,
                                       uint32_t addr) {
    asm volatile("ldmatrix.sync.aligned.m8n8.x4.trans.shared.b16 {%0,%1,%2,%3}, [%4];"
                 : "=r"(r0), "=r"(r1), "=r"(r2), "=r"(r3) : "r"(addr));
}

// ---------------------------------------------------------------------------
// fp16 MMA GEMM: C(MxN)=A(MxK)*B(KxN), K=256, tile 128x128x32, inline
// fp32->fp16 cvt on load, ldmatrix operands, m16n8k16.
// 256 threads = 8 warps (4m x 2n), warp tile 32x64.
// ---------------------------------------------------------------------------
#define GBM 128
#define GBN 128
#define GBK 32
#define APH 40    // As pitch in halves (32+8): ldsm rows 5 chunks apart -> conflict-free
#define BPH 136   // Bs pitch in halves (128+8): 17 chunks -> conflict-free

struct GemmAcc { float acc[2][8][4]; };

__device__ __forceinline__ void gemm_core(__half* As, __half* Bs,
                                          const float* __restrict__ Ag,
                                          const float* __restrict__ Bg,
                                          int m0, int n0, GemmAcc& R)
{
    const int tid = threadIdx.x;
    const int warp = tid >> 5;
    const int lane = tid & 31;
    const int wm = (warp >> 1) * 32;
    const int wn = (warp & 1) * 64;
    const uint32_t as_b = (uint32_t)__cvta_generic_to_shared(As);
    const uint32_t bs_b = (uint32_t)__cvta_generic_to_shared(Bs);

    #pragma unroll
    for (int mt = 0; mt < 2; mt++)
        #pragma unroll
        for (int nt = 0; nt < 8; nt++)
            #pragma unroll
            for (int r = 0; r < 4; r++) R.acc[mt][nt][r] = 0.f;

    for (int k0 = 0; k0 < CDIM; k0 += GBK) {
        // A tile 128x32 fp32 -> fp16
        #pragma unroll
        for (int i = 0; i < 4; i++) {
            int slot = i * 256 + tid;
            int row = slot >> 3, f4 = slot & 7;
            float4 a = *(const float4*)&Ag[(m0 + row) * CDIM + k0 + 4 * f4];
            uint2 hh;
            hh.x = f2h2(a.x, a.y); hh.y = f2h2(a.z, a.w);
            *(uint2*)&As[row * APH + 4 * f4] = hh;
        }
        // B tile 32x128 fp32 -> fp16
        #pragma unroll
        for (int i = 0; i < 4; i++) {
            int slot = i * 256 + tid;
            int row = slot >> 5, f4 = slot & 31;
            float4 bv = *(const float4*)&Bg[(k0 + row) * NN + n0 + 4 * f4];
            uint2 hh;
            hh.x = f2h2(bv.x, bv.y); hh.y = f2h2(bv.z, bv.w);
            *(uint2*)&Bs[row * BPH + 4 * f4] = hh;
        }
        __syncthreads();

        #pragma unroll
        for (int ks = 0; ks < 2; ks++) {
            int kk = 16 * ks;
            // A frags: non-trans ldsm on [m][k] rows
            uint32_t af[2][4];
            #pragma unroll
            for (int mt = 0; mt < 2; mt++) {
                int r = wm + 16 * mt + (lane & 7) + 8 * ((lane >> 3) & 1);
                int c = kk + 8 * ((lane >> 4) & 1);
                ldsm4(af[mt][0], af[mt][1], af[mt][2], af[mt][3],
                      as_b + (uint32_t)(r * APH + c) * 2);
            }
            // B frags: trans ldsm on [k][n] rows; mma
            #pragma unroll
            for (int nb = 0; nb < 4; nb++) {
                int kr = kk + (lane & 7) + 8 * ((lane >> 3) & 1);
                int nc = wn + 16 * nb + 8 * ((lane >> 4) & 1);
                uint32_t b0, b1, b2, b3;
                ldsm4t(b0, b1, b2, b3, bs_b + (uint32_t)(kr * BPH + nc) * 2);
                mma_f16(R.acc[0][2 * nb],     af[0][0], af[0][1], af[0][2], af[0][3], b0, b1);
                mma_f16(R.acc[0][2 * nb + 1], af[0][0], af[0][1], af[0][2], af[0][3], b2, b3);
                mma_f16(R.acc[1][2 * nb],     af[1][0], af[1][1], af[1][2], af[1][3], b0, b1);
                mma_f16(R.acc[1][2 * nb + 1], af[1][0], af[1][1], af[1][2], af[1][3], b2, b3);
            }
        }
        __syncthreads();
    }
}

// Kernel 1: QKV projection; writes fp16 [b][h][d][n] Q/K/V (Q pre-scaled).
__global__ __launch_bounds__(256) void qkv_gemm_kernel(
    const float* __restrict__ W,   // [768, 256]
    const float* __restrict__ X)   // [B, 256, 1024]
{
    __shared__ __half As[GBM * APH];
    __shared__ __half Bs[GBK * BPH];
    const int b = blockIdx.z;
    const int m0 = blockIdx.y * GBM;
    const int n0 = blockIdx.x * GBN;

    GemmAcc R;
    gemm_core(As, Bs, W, X + (size_t)b * CDIM * NN, m0, n0, R);

    const int tid = threadIdx.x;
    const int warp = tid >> 5, lane = tid & 31;
    const int g = lane >> 2, tig = lane & 3;
    const int wm = (warp >> 1) * 32, wn = (warp & 1) * 64;

    #pragma unroll
    for (int mt = 0; mt < 2; mt++) {
        #pragma unroll
        for (int half = 0; half < 2; half++) {
            int o = m0 + wm + 16 * mt + g + 8 * half;
            int grp = o >> 8;
            int hh = (o >> 5) & 7;
            int dd = o & 31;
            __half* dst = (grp == 0) ? g_qh : (grp == 1) ? g_kh : g_vh;
            float sc = (grp == 0) ? SCALE_F : 1.0f;
            __half* rowp = dst + ((size_t)(b * NH + hh) * ND + dd) * NN;
            #pragma unroll
            for (int nt = 0; nt < 8; nt++) {
                int n = n0 + wn + 8 * nt + 2 * tig;
                *(uint32_t*)&rowp[n] =
                    f2h2(R.acc[mt][nt][2 * half] * sc, R.acc[mt][nt][2 * half + 1] * sc);
            }
        }
    }
}

// Kernel 3: output projection + bias (B = g_ao fp32 [c][n], inline cvt).
__global__ __launch_bounds__(256) void out_gemm_kernel(
    const float* __restrict__ W,     // [256, 256]
    const float* __restrict__ bias,  // [256]
    float* __restrict__ Y)           // [B, 256, 1024]
{
    __shared__ __half As[GBM * APH];
    __shared__ __half Bs[GBK * BPH];
    const int b = blockIdx.z;
    const int m0 = blockIdx.y * GBM;
    const int n0 = blockIdx.x * GBN;

    GemmAcc R;
    gemm_core(As, Bs, W, g_ao + (size_t)b * CDIM * NN, m0, n0, R);

    const int tid = threadIdx.x;
    const int warp = tid >> 5, lane = tid & 31;
    const int g = lane >> 2, tig = lane & 3;
    const int wm = (warp >> 1) * 32, wn = (warp & 1) * 64;

    #pragma unroll
    for (int mt = 0; mt < 2; mt++) {
        #pragma unroll
        for (int half = 0; half < 2; half++) {
            int o = m0 + wm + 16 * mt + g + 8 * half;
            float bv = bias[o];
            float* yrow = Y + ((size_t)b * CDIM + o) * NN;
            #pragma unroll
            for (int nt = 0; nt < 8; nt++) {
                int n = n0 + wn + 8 * nt + 2 * tig;
                yrow[n]     = R.acc[mt][nt][2 * half]     + bv;
                yrow[n + 1] = R.acc[mt][nt][2 * half + 1] + bv;
            }
        }
    }
}

// ---------------------------------------------------------------------------
// Kernel 2: fp16 flash attention, no-max softmax, P packed straight from
// S-accumulators into PV A-fragments (no smem, no shuffles).
// 128 threads (4 warps), Br=64 (16 rows/warp), Bc=64, d=32.
// Q/K/V stored [d][n] fp16; ldmatrix .trans for Q(A) and K(B),
// non-trans for V(B). Static smem 13.5KB -> 3 CTAs/SM.
// ---------------------------------------------------------------------------
#define BR   64
#define BC   64
#define TPH  72   // tile pitch in halves (64+8): rows 9 chunks apart -> conflict-free
#define NTILES (NN / BC)   // 16

__global__ __launch_bounds__(128) void attn_kernel()
{
    __shared__ __half Qs[ND * TPH];
    __shared__ __half Ks[ND * TPH];
    __shared__ __half Vs[ND * TPH];

    const int b = blockIdx.z;
    const int h = blockIdx.y;
    const int q0 = blockIdx.x * BR;

    const int tid = threadIdx.x;
    const int warp = tid >> 5, lane = tid & 31;
    const int g = lane >> 2, tig = lane & 3;

    const size_t headBase = (size_t)(b * NH + h) * ND * NN;
    const __half* Qg = g_qh + headBase;   // [d][n]
    const __half* Kg = g_kh + headBase;   // [d][n]
    const __half* Vg = g_vh + headBase;   // [d][n]
    const uint32_t qs_b = (uint32_t)__cvta_generic_to_shared(Qs);
    const uint32_t ks_b = (uint32_t)__cvta_generic_to_shared(Ks);
    const uint32_t vs_b = (uint32_t)__cvta_generic_to_shared(Vs);

    // Load Q tile: 32 d-rows x 64 cols (q0..q0+63) = 256 16B chunks
    #pragma unroll
    for (int i = 0; i < 2; i++) {
        int slot = i * 128 + tid;
        int row = slot >> 3, c = (slot & 7) * 8;
        *(uint4*)&Qs[row * TPH + c] = *(const uint4*)&Qg[(size_t)row * NN + q0 + c];
    }
    __syncthreads();

    // Q A-frags via ldsm.trans ([k][m] storage): warp rows i = 16*warp..+15
    uint32_t qf[2][4];
    const int ib = 16 * warp;
    #pragma unroll
    for (int ks = 0; ks < 2; ks++) {
        int dr = 16 * ks + (lane & 7) + 8 * ((lane >> 4) & 1);
        int ic = ib + 8 * ((lane >> 3) & 1);
        ldsm4t(qf[ks][0], qf[ks][1], qf[ks][2], qf[ks][3],
               qs_b + (uint32_t)(dr * TPH + ic) * 2);
    }

    float oacc[4][4];
    #pragma unroll
    for (int dt = 0; dt < 4; dt++)
        #pragma unroll
        for (int r = 0; r < 4; r++) oacc[dt][r] = 0.f;
    float sum0 = 0.f, sum1 = 0.f;

    for (int t = 0; t < NTILES; t++) {
        int j0 = t * BC;
        __syncthreads();  // prior iter done reading Ks/Vs
        #pragma unroll
        for (int i = 0; i < 2; i++) {
            int slot = i * 128 + tid;
            int row = slot >> 3, c = (slot & 7) * 8;
            *(uint4*)&Ks[row * TPH + c] = *(const uint4*)&Kg[(size_t)row * NN + j0 + c];
            *(uint4*)&Vs[row * TPH + c] = *(const uint4*)&Vg[(size_t)row * NN + j0 + c];
        }
        __syncthreads();

        // S = Q K^T : [16 x 64] per warp. B-frags via ldsm.trans on Ks [k=d][n=j].
        float sacc[8][4];
        #pragma unroll
        for (int nt = 0; nt < 8; nt++)
            #pragma unroll
            for (int r = 0; r < 4; r++) sacc[nt][r] = 0.f;
        #pragma unroll
        for (int ks = 0; ks < 2; ks++) {
            int kk = 16 * ks;
            #pragma unroll
            for (int nb = 0; nb < 4; nb++) {
                int kr = kk + (lane & 7) + 8 * ((lane >> 3) & 1);
                int jc = 16 * nb + 8 * ((lane >> 4) & 1);
                uint32_t b0, b1, b2, b3;
                ldsm4t(b0, b1, b2, b3, ks_b + (uint32_t)(kr * TPH + jc) * 2);
                mma_f16(sacc[2 * nb],     qf[ks][0], qf[ks][1], qf[ks][2], qf[ks][3], b0, b1);
                mma_f16(sacc[2 * nb + 1], qf[ks][0], qf[ks][1], qf[ks][2], qf[ks][3], b2, b3);
            }
        }

        // p = exp2(s*log2e); accumulate sums; pack directly into PV A-frags
        uint32_t pa[8][2];
        #pragma unroll
        for (int nt = 0; nt < 8; nt++) {
            float p0 = ex2f(sacc[nt][0] * L2E);
            float p1 = ex2f(sacc[nt][1] * L2E);
            float p2 = ex2f(sacc[nt][2] * L2E);
            float p3 = ex2f(sacc[nt][3] * L2E);
            sum0 += p0 + p1;
            sum1 += p2 + p3;
            pa[nt][0] = f2h2(p0, p1);   // rows g,   cols 2tig..
            pa[nt][1] = f2h2(p2, p3);   // rows g+8, cols 2tig..
        }

        // O += P V : A = packed P frags; B via non-trans ldsm on Vs [n=d][k=j].
        #pragma unroll
        for (int ks2 = 0; ks2 < 4; ks2++) {
            uint32_t a0 = pa[2 * ks2][0],     a1 = pa[2 * ks2][1];
            uint32_t a2 = pa[2 * ks2 + 1][0], a3 = pa[2 * ks2 + 1][1];
            #pragma unroll
            for (int db = 0; db < 2; db++) {
                int dr = 16 * db + (lane & 7) + 8 * ((lane >> 4) & 1);
                int jc = 16 * ks2 + 8 * ((lane >> 3) & 1);
                uint32_t b0, b1, b2, b3;
                ldsm4(b0, b1, b2, b3, vs_b + (uint32_t)(dr * TPH + jc) * 2);
                mma_f16(oacc[2 * db],     a0, a1, a2, a3, b0, b1);
                mma_f16(oacc[2 * db + 1], a0, a1, a2, a3, b2, b3);
            }
        }
    }

    // Final row-sum reduction across the 4-thread group, normalize, store.
    sum0 += __shfl_xor_sync(0xffffffff, sum0, 1);
    sum0 += __shfl_xor_sync(0xffffffff, sum0, 2);
    sum1 += __shfl_xor_sync(0xffffffff, sum1, 1);
    sum1 += __shfl_xor_sync(0xffffffff, sum1, 2);
    float inv0 = 1.0f / sum0;
    float inv1 = 1.0f / sum1;

    int n_row0 = q0 + 16 * warp + g;
    float* aoB = g_ao + ((size_t)b * CDIM + h * ND) * NN;
    #pragma unroll
    for (int dt = 0; dt < 4; dt++) {
        int d = 8 * dt + 2 * tig;
        aoB[(size_t)d * NN + n_row0]           = oacc[dt][0] * inv0;
        aoB[(size_t)(d + 1) * NN + n_row0]     = oacc[dt][1] * inv0;
        aoB[(size_t)d * NN + n_row0 + 8]       = oacc[dt][2] * inv1;
        aoB[(size_t)(d + 1) * NN + n_row0 + 8] = oacc[dt][3] * inv1;
    }
}

// ---------------------------------------------------------------------------
extern "C" void kernel_launch(void* const* d_in, const int* in_sizes, int n_in,
                              void* d_out, int out_size)
{
    const float* x     = (const float*)d_in[0];
    const float* w_qkv = (const float*)d_in[1];
    const float* w_out = (const float*)d_in[2];
    const float* b_out = (const float*)d_in[3];
    float* y = (float*)d_out;

    qkv_gemm_kernel<<<dim3(NN / GBN, QKV_M / GBM, NB), 256>>>(w_qkv, x);
    attn_kernel<<<dim3(NN / BR, NH, NB), 128>>>();
    out_gemm_kernel<<<dim3(NN / GBN, CDIM / GBM, NB), 256>>>(w_out, b_out, y);
}

// round 11
// speedup vs baseline: 2.4494x; 1.0694x over previous
#include <cuda_runtime.h>
#include <cuda_fp16.h>
#include <cstdint>

// Problem constants
#define NB   8
#define NH   8
#define ND   32
#define NN   1024
#define CDIM 256
#define QKV_M 768
#define SCALE_F 0.17677669529663687f
#define L2E 1.4426950408889634f

// Scratch (device globals — no allocation allowed)
__device__ __half g_xh[NB * CDIM * NN];    // fp16 X, [b][c][n]
__device__ __half g_wqh[QKV_M * CDIM];     // fp16 w_qkv, [o][c]
__device__ __half g_woh[CDIM * CDIM];      // fp16 w_out, [o][c]
__device__ __half g_qh[NB * NH * ND * NN]; // fp16 Q (scaled), [b][h][d][n]
__device__ __half g_kh[NB * NH * ND * NN]; // fp16 K, [b][h][d][n]
__device__ __half g_vh[NB * NH * ND * NN]; // fp16 V, [b][h][d][n]
__device__ __half g_aoh[NB * CDIM * NN];   // fp16 attention out, [b][c][n]

// ---------------------------------------------------------------------------
// helpers
// ---------------------------------------------------------------------------
__device__ __forceinline__ uint32_t f2h2(float lo, float hi) {
    uint32_t r;
    asm("cvt.rn.f16x2.f32 %0, %1, %2;" : "=r"(r) : "f"(hi), "f"(lo));
    return r;
}

__device__ __forceinline__ float ex2f(float x) {
    float r;
    asm("ex2.approx.ftz.f32 %0, %1;" : "=f"(r) : "f"(x));
    return r;
}

__device__ __forceinline__ void mma_f16(float c[4],
                                        uint32_t a0, uint32_t a1, uint32_t a2, uint32_t a3,
                                        uint32_t b0, uint32_t b1) {
    asm volatile(
        "mma.sync.aligned.m16n8k16.row.col.f32.f16.f16.f32 "
        "{%0,%1,%2,%3}, {%4,%5,%6,%7}, {%8,%9}, {%0,%1,%2,%3};\n"
        : "+f"(c[0]), "+f"(c[1]), "+f"(c[2]), "+f"(c[3])
        : "r"(a0), "r"(a1), "r"(a2), "r"(a3), "r"(b0), "r"(b1));
}

__device__ __forceinline__ void ldsm4(uint32_t& r0, uint32_t& r1, uint32_t& r2, uint32_t& r3,
                                      uint32_t addr) {
    asm volatile("ldmatrix.sync.aligned.m8n8.x4.shared.b16 {%0,%1,%2,%3}, [%4];"
                 : "=r"(r0), "=r"(r1), "=r"(r2), "=r"(r3) : "r"(addr));
}

__device__ __forceinline__ void ldsm4t(uint32_t& r0, uint32_t& r1, uint32_t& r2, uint32_t& r3,
                                       uint32_t addr) {
    asm volatile("ldmatrix.sync.aligned.m8n8.x4.trans.shared.b16 {%0,%1,%2,%3}, [%4];"
                 : "=r"(r0), "=r"(r1), "=r"(r2), "=r"(r3) : "r"(addr));
}

__device__ __forceinline__ void cp16(uint32_t dst_smem, const void* src) {
    asm volatile("cp.async.cg.shared.global [%0], [%1], 16;\n" :: "r"(dst_smem), "l"(src));
}
__device__ __forceinline__ void cp_commit() { asm volatile("cp.async.commit_group;\n"); }
__device__ __forceinline__ void cp_wait1() { asm volatile("cp.async.wait_group 1;\n"); }
__device__ __forceinline__ void cp_wait0() { asm volatile("cp.async.wait_group 0;\n"); }

// ---------------------------------------------------------------------------
// Kernel 0: fp32 -> fp16 conversion of X, w_qkv, w_out
// ---------------------------------------------------------------------------
#define NX4  (NB * CDIM * NN / 4)   // 524288
#define NWQ4 (QKV_M * CDIM / 4)     // 49152
#define NWO4 (CDIM * CDIM / 4)      // 16384
#define CVT4 (NX4 + NWQ4 + NWO4)    // 589824

__global__ __launch_bounds__(256) void cvt_kernel(const float* __restrict__ x,
                                                  const float* __restrict__ wq,
                                                  const float* __restrict__ wo)
{
    int idx = blockIdx.x * 256 + threadIdx.x;
    if (idx >= CVT4) return;
    const float4* src; __half* dst; int j;
    if (idx < NX4)             { src = (const float4*)x;  dst = g_xh;  j = idx; }
    else if (idx < NX4 + NWQ4) { src = (const float4*)wq; dst = g_wqh; j = idx - NX4; }
    else                       { src = (const float4*)wo; dst = g_woh; j = idx - NX4 - NWQ4; }
    float4 v = src[j];
    uint2 hh;
    hh.x = f2h2(v.x, v.y); hh.y = f2h2(v.z, v.w);
    *(uint2*)&dst[4 * j] = hh;
}

// ---------------------------------------------------------------------------
// fp16 MMA GEMM: C(MxN)=A(MxK)*B(KxN), K=256, tile 128x128x32,
// cp.async 2-stage double buffer on pre-converted fp16 operands.
// 256 threads = 8 warps (4m x 2n), warp tile 32x64.
// ---------------------------------------------------------------------------
#define GBM 128
#define GBN 128
#define GBK 32
#define APH 40    // As pitch (halves): 32+8
#define BPH 136   // Bs pitch (halves): 128+8
#define A_STG (GBM * APH)
#define B_STG (GBK * BPH)
#define KTILES (CDIM / GBK)   // 8

struct GemmAcc { float acc[2][8][4]; };

__device__ __forceinline__ void gemm_issue(uint32_t as_b, uint32_t bs_b, int s,
                                           const __half* __restrict__ Ag,
                                           const __half* __restrict__ Bg,
                                           int m0, int n0, int k0, int tid)
{
    // A tile 128x32 halves: 4 chunks (16B) per row, 512 total -> 2/thread
    #pragma unroll
    for (int i = 0; i < 2; i++) {
        int slot = i * 256 + tid;
        int row = slot >> 2, c = (slot & 3) * 8;
        cp16(as_b + (uint32_t)(s * A_STG + row * APH + c) * 2,
             Ag + (size_t)(m0 + row) * CDIM + k0 + c);
    }
    // B tile 32x128 halves: 16 chunks per row, 512 total -> 2/thread
    #pragma unroll
    for (int i = 0; i < 2; i++) {
        int slot = i * 256 + tid;
        int row = slot >> 4, c = (slot & 15) * 8;
        cp16(bs_b + (uint32_t)(s * B_STG + row * BPH + c) * 2,
             Bg + (size_t)(k0 + row) * NN + n0 + c);
    }
    cp_commit();
}

__device__ __forceinline__ void gemm_core(__half* As, __half* Bs,
                                          const __half* __restrict__ Ag,
                                          const __half* __restrict__ Bg,
                                          int m0, int n0, GemmAcc& R)
{
    const int tid = threadIdx.x;
    const int warp = tid >> 5;
    const int lane = tid & 31;
    const int wm = (warp >> 1) * 32;
    const int wn = (warp & 1) * 64;
    const uint32_t as_b = (uint32_t)__cvta_generic_to_shared(As);
    const uint32_t bs_b = (uint32_t)__cvta_generic_to_shared(Bs);

    #pragma unroll
    for (int mt = 0; mt < 2; mt++)
        #pragma unroll
        for (int nt = 0; nt < 8; nt++)
            #pragma unroll
            for (int r = 0; r < 4; r++) R.acc[mt][nt][r] = 0.f;

    gemm_issue(as_b, bs_b, 0, Ag, Bg, m0, n0, 0, tid);

    #pragma unroll 1
    for (int kt = 0; kt < KTILES; kt++) {
        if (kt < KTILES - 1) {
            gemm_issue(as_b, bs_b, (kt + 1) & 1, Ag, Bg, m0, n0, (kt + 1) * GBK, tid);
            cp_wait1();
        } else {
            cp_wait0();
        }
        __syncthreads();

        const uint32_t a_base = as_b + (uint32_t)((kt & 1) * A_STG) * 2;
        const uint32_t b_base = bs_b + (uint32_t)((kt & 1) * B_STG) * 2;

        #pragma unroll
        for (int ks = 0; ks < 2; ks++) {
            int kk = 16 * ks;
            uint32_t af[2][4];
            #pragma unroll
            for (int mt = 0; mt < 2; mt++) {
                int r = wm + 16 * mt + (lane & 7) + 8 * ((lane >> 3) & 1);
                int c = kk + 8 * ((lane >> 4) & 1);
                ldsm4(af[mt][0], af[mt][1], af[mt][2], af[mt][3],
                      a_base + (uint32_t)(r * APH + c) * 2);
            }
            #pragma unroll
            for (int nb = 0; nb < 4; nb++) {
                int kr = kk + (lane & 7) + 8 * ((lane >> 3) & 1);
                int nc = wn + 16 * nb + 8 * ((lane >> 4) & 1);
                uint32_t b0, b1, b2, b3;
                ldsm4t(b0, b1, b2, b3, b_base + (uint32_t)(kr * BPH + nc) * 2);
                mma_f16(R.acc[0][2 * nb],     af[0][0], af[0][1], af[0][2], af[0][3], b0, b1);
                mma_f16(R.acc[0][2 * nb + 1], af[0][0], af[0][1], af[0][2], af[0][3], b2, b3);
                mma_f16(R.acc[1][2 * nb],     af[1][0], af[1][1], af[1][2], af[1][3], b0, b1);
                mma_f16(R.acc[1][2 * nb + 1], af[1][0], af[1][1], af[1][2], af[1][3], b2, b3);
            }
        }
        __syncthreads();
    }
}

// Kernel 1: QKV projection; writes fp16 [b][h][d][n] Q/K/V (Q pre-scaled).
__global__ __launch_bounds__(256) void qkv_gemm_kernel()
{
    __shared__ __half As[2 * A_STG];
    __shared__ __half Bs[2 * B_STG];
    const int b = blockIdx.z;
    const int m0 = blockIdx.y * GBM;
    const int n0 = blockIdx.x * GBN;

    GemmAcc R;
    gemm_core(As, Bs, g_wqh, g_xh + (size_t)b * CDIM * NN, m0, n0, R);

    const int tid = threadIdx.x;
    const int warp = tid >> 5, lane = tid & 31;
    const int g = lane >> 2, tig = lane & 3;
    const int wm = (warp >> 1) * 32, wn = (warp & 1) * 64;

    #pragma unroll
    for (int mt = 0; mt < 2; mt++) {
        #pragma unroll
        for (int half = 0; half < 2; half++) {
            int o = m0 + wm + 16 * mt + g + 8 * half;
            int grp = o >> 8;
            int hh = (o >> 5) & 7;
            int dd = o & 31;
            __half* dst = (grp == 0) ? g_qh : (grp == 1) ? g_kh : g_vh;
            float sc = (grp == 0) ? SCALE_F : 1.0f;
            __half* rowp = dst + ((size_t)(b * NH + hh) * ND + dd) * NN;
            #pragma unroll
            for (int nt = 0; nt < 8; nt++) {
                int n = n0 + wn + 8 * nt + 2 * tig;
                *(uint32_t*)&rowp[n] =
                    f2h2(R.acc[mt][nt][2 * half] * sc, R.acc[mt][nt][2 * half + 1] * sc);
            }
        }
    }
}

// Kernel 3: output projection + bias (A = w_out fp16, B = g_aoh fp16).
__global__ __launch_bounds__(256) void out_gemm_kernel(
    const float* __restrict__ bias,  // [256]
    float* __restrict__ Y)           // [B, 256, 1024]
{
    __shared__ __half As[2 * A_STG];
    __shared__ __half Bs[2 * B_STG];
    const int b = blockIdx.z;
    const int m0 = blockIdx.y * GBM;
    const int n0 = blockIdx.x * GBN;

    GemmAcc R;
    gemm_core(As, Bs, g_woh, g_aoh + (size_t)b * CDIM * NN, m0, n0, R);

    const int tid = threadIdx.x;
    const int warp = tid >> 5, lane = tid & 31;
    const int g = lane >> 2, tig = lane & 3;
    const int wm = (warp >> 1) * 32, wn = (warp & 1) * 64;

    #pragma unroll
    for (int mt = 0; mt < 2; mt++) {
        #pragma unroll
        for (int half = 0; half < 2; half++) {
            int o = m0 + wm + 16 * mt + g + 8 * half;
            float bv = bias[o];
            float* yrow = Y + ((size_t)b * CDIM + o) * NN;
            #pragma unroll
            for (int nt = 0; nt < 8; nt++) {
                int n = n0 + wn + 8 * nt + 2 * tig;
                yrow[n]     = R.acc[mt][nt][2 * half]     + bv;
                yrow[n + 1] = R.acc[mt][nt][2 * half + 1] + bv;
            }
        }
    }
}

// ---------------------------------------------------------------------------
// Kernel 2: fp16 flash attention, no-max softmax, direct P-packing,
// cp.async double-buffered K/V tiles. 128 threads (4 warps), Br=64, Bc=64.
// Q/K/V stored [d][n] fp16. Static smem 23KB.
// ---------------------------------------------------------------------------
#define BR   64
#define BC   64
#define TPH  72   // tile pitch in halves (64+8)
#define T_STG (ND * TPH)
#define NTILES (NN / BC)   // 16

__device__ __forceinline__ void attn_issue(uint32_t ks_b, uint32_t vs_b, int s,
                                           const __half* __restrict__ Kg,
                                           const __half* __restrict__ Vg,
                                           int j0, int tid)
{
    // K,V tiles: 32 d-rows x 64 halves (8 chunks/row) = 256 chunks each
    #pragma unroll
    for (int i = 0; i < 2; i++) {
        int slot = i * 128 + tid;
        int row = slot >> 3, c = (slot & 7) * 8;
        cp16(ks_b + (uint32_t)(s * T_STG + row * TPH + c) * 2,
             Kg + (size_t)row * NN + j0 + c);
        cp16(vs_b + (uint32_t)(s * T_STG + row * TPH + c) * 2,
             Vg + (size_t)row * NN + j0 + c);
    }
    cp_commit();
}

__global__ __launch_bounds__(128) void attn_kernel()
{
    __shared__ __half Qs[T_STG];
    __shared__ __half Ks[2 * T_STG];
    __shared__ __half Vs[2 * T_STG];

    const int b = blockIdx.z;
    const int h = blockIdx.y;
    const int q0 = blockIdx.x * BR;

    const int tid = threadIdx.x;
    const int warp = tid >> 5, lane = tid & 31;
    const int g = lane >> 2, tig = lane & 3;

    const size_t headBase = (size_t)(b * NH + h) * ND * NN;
    const __half* Qg = g_qh + headBase;   // [d][n]
    const __half* Kg = g_kh + headBase;   // [d][n]
    const __half* Vg = g_vh + headBase;   // [d][n]
    const uint32_t qs_b = (uint32_t)__cvta_generic_to_shared(Qs);
    const uint32_t ks_b = (uint32_t)__cvta_generic_to_shared(Ks);
    const uint32_t vs_b = (uint32_t)__cvta_generic_to_shared(Vs);

    // Prefetch K/V tile 0, then load Q tile (32 d-rows x 64 cols)
    attn_issue(ks_b, vs_b, 0, Kg, Vg, 0, tid);
    #pragma unroll
    for (int i = 0; i < 2; i++) {
        int slot = i * 128 + tid;
        int row = slot >> 3, c = (slot & 7) * 8;
        *(uint4*)&Qs[row * TPH + c] = *(const uint4*)&Qg[(size_t)row * NN + q0 + c];
    }
    __syncthreads();

    // Q A-frags via ldsm.trans ([k=d][m=i] storage): warp rows 16*warp..+15
    uint32_t qf[2][4];
    const int ib = 16 * warp;
    #pragma unroll
    for (int ks = 0; ks < 2; ks++) {
        int dr = 16 * ks + (lane & 7) + 8 * ((lane >> 4) & 1);
        int ic = ib + 8 * ((lane >> 3) & 1);
        ldsm4t(qf[ks][0], qf[ks][1], qf[ks][2], qf[ks][3],
               qs_b + (uint32_t)(dr * TPH + ic) * 2);
    }

    float oacc[4][4];
    #pragma unroll
    for (int dt = 0; dt < 4; dt++)
        #pragma unroll
        for (int r = 0; r < 4; r++) oacc[dt][r] = 0.f;
    float sum0 = 0.f, sum1 = 0.f;

    #pragma unroll 1
    for (int t = 0; t < NTILES; t++) {
        if (t < NTILES - 1) {
            attn_issue(ks_b, vs_b, (t + 1) & 1, Kg, Vg, (t + 1) * BC, tid);
            cp_wait1();
        } else {
            cp_wait0();
        }
        __syncthreads();

        const uint32_t kb = ks_b + (uint32_t)((t & 1) * T_STG) * 2;
        const uint32_t vb = vs_b + (uint32_t)((t & 1) * T_STG) * 2;

        // S = Q K^T : [16 x 64] per warp (ldsm.trans on K [d][j])
        float sacc[8][4];
        #pragma unroll
        for (int nt = 0; nt < 8; nt++)
            #pragma unroll
            for (int r = 0; r < 4; r++) sacc[nt][r] = 0.f;
        #pragma unroll
        for (int ks = 0; ks < 2; ks++) {
            int kk = 16 * ks;
            #pragma unroll
            for (int nb = 0; nb < 4; nb++) {
                int kr = kk + (lane & 7) + 8 * ((lane >> 3) & 1);
                int jc = 16 * nb + 8 * ((lane >> 4) & 1);
                uint32_t b0, b1, b2, b3;
                ldsm4t(b0, b1, b2, b3, kb + (uint32_t)(kr * TPH + jc) * 2);
                mma_f16(sacc[2 * nb],     qf[ks][0], qf[ks][1], qf[ks][2], qf[ks][3], b0, b1);
                mma_f16(sacc[2 * nb + 1], qf[ks][0], qf[ks][1], qf[ks][2], qf[ks][3], b2, b3);
            }
        }

        // p = exp2(s*log2e); accumulate sums; pack directly into PV A-frags
        uint32_t pa[8][2];
        #pragma unroll
        for (int nt = 0; nt < 8; nt++) {
            float p0 = ex2f(sacc[nt][0] * L2E);
            float p1 = ex2f(sacc[nt][1] * L2E);
            float p2 = ex2f(sacc[nt][2] * L2E);
            float p3 = ex2f(sacc[nt][3] * L2E);
            sum0 += p0 + p1;
            sum1 += p2 + p3;
            pa[nt][0] = f2h2(p0, p1);
            pa[nt][1] = f2h2(p2, p3);
        }

        // O += P V (non-trans ldsm on V [d][j])
        #pragma unroll
        for (int ks2 = 0; ks2 < 4; ks2++) {
            uint32_t a0 = pa[2 * ks2][0],     a1 = pa[2 * ks2][1];
            uint32_t a2 = pa[2 * ks2 + 1][0], a3 = pa[2 * ks2 + 1][1];
            #pragma unroll
            for (int db = 0; db < 2; db++) {
                int dr = 16 * db + (lane & 7) + 8 * ((lane >> 4) & 1);
                int jc = 16 * ks2 + 8 * ((lane >> 3) & 1);
                uint32_t b0, b1, b2, b3;
                ldsm4(b0, b1, b2, b3, vb + (uint32_t)(dr * TPH + jc) * 2);
                mma_f16(oacc[2 * db],     a0, a1, a2, a3, b0, b1);
                mma_f16(oacc[2 * db + 1], a0, a1, a2, a3, b2, b3);
            }
        }
        __syncthreads();
    }

    // Final row-sum reduction, normalize, store fp16 [b][c][n].
    sum0 += __shfl_xor_sync(0xffffffff, sum0, 1);
    sum0 += __shfl_xor_sync(0xffffffff, sum0, 2);
    sum1 += __shfl_xor_sync(0xffffffff, sum1, 1);
    sum1 += __shfl_xor_sync(0xffffffff, sum1, 2);
    float inv0 = 1.0f / sum0;
    float inv1 = 1.0f / sum1;

    int n_row0 = q0 + 16 * warp + g;
    __half* aoB = g_aoh + ((size_t)b * CDIM + h * ND) * NN;
    #pragma unroll
    for (int dt = 0; dt < 4; dt++) {
        int d = 8 * dt + 2 * tig;
        aoB[(size_t)d * NN + n_row0]           = __float2half_rn(oacc[dt][0] * inv0);
        aoB[(size_t)(d + 1) * NN + n_row0]     = __float2half_rn(oacc[dt][1] * inv0);
        aoB[(size_t)d * NN + n_row0 + 8]       = __float2half_rn(oacc[dt][2] * inv1);
        aoB[(size_t)(d + 1) * NN + n_row0 + 8] = __float2half_rn(oacc[dt][3] * inv1);
    }
}

// ---------------------------------------------------------------------------
extern "C" void kernel_launch(void* const* d_in, const int* in_sizes, int n_in,
                              void* d_out, int out_size)
{
    const float* x     = (const float*)d_in[0];
    const float* w_qkv = (const float*)d_in[1];
    const float* w_out = (const float*)d_in[2];
    const float* b_out = (const float*)d_in[3];
    float* y = (float*)d_out;

    cvt_kernel<<<(CVT4 + 255) / 256, 256>>>(x, w_qkv, w_out);
    qkv_gemm_kernel<<<dim3(NN / GBN, QKV_M / GBM, NB), 256>>>();
    attn_kernel<<<dim3(NN / BR, NH, NB), 128>>>();
    out_gemm_kernel<<<dim3(NN / GBN, CDIM / GBM, NB), 256>>>(b_out, y);
}

// round 13
// speedup vs baseline: 2.5221x; 1.0297x over previous
#include <cuda_runtime.h>
#include <cuda_fp16.h>
#include <cstdint>

// Problem constants
#define NB   8
#define NH   8
#define ND   32
#define NN   1024
#define CDIM 256
#define QKV_M 768
#define SCALE_F 0.17677669529663687f
#define L2E 1.4426950408889634f
#define QSCALE (SCALE_F * L2E)   // fold log2(e) into Q

// Scratch (device globals — no allocation allowed)
__device__ __half g_xh[NB * CDIM * NN];    // fp16 X, [b][c][n]
__device__ __half g_wqh[QKV_M * CDIM];     // fp16 w_qkv, [o][c]
__device__ __half g_woh[CDIM * CDIM];      // fp16 w_out, [o][c]
__device__ __half g_qh[NB * NH * ND * NN]; // fp16 Q (scaled*L2E), [b][h][d][n]
__device__ __half g_kh[NB * NH * ND * NN]; // fp16 K, [b][h][d][n]
__device__ __half g_vh[NB * NH * ND * NN]; // fp16 V, [b][h][d][n]
__device__ __half g_aoh[NB * CDIM * NN];   // fp16 attention out, [b][c][n]

// ---------------------------------------------------------------------------
// helpers
// ---------------------------------------------------------------------------
__device__ __forceinline__ uint32_t f2h2(float lo, float hi) {
    uint32_t r;
    asm("cvt.rn.f16x2.f32 %0, %1, %2;" : "=r"(r) : "f"(hi), "f"(lo));
    return r;
}

__device__ __forceinline__ uint32_t ex2h2(uint32_t x) {
    uint32_t r;
    asm("ex2.approx.f16x2 %0, %1;" : "=r"(r) : "r"(x));
    return r;
}

__device__ __forceinline__ void mma_f16(float c[4],
                                        uint32_t a0, uint32_t a1, uint32_t a2, uint32_t a3,
                                        uint32_t b0, uint32_t b1) {
    asm volatile(
        "mma.sync.aligned.m16n8k16.row.col.f32.f16.f16.f32 "
        "{%0,%1,%2,%3}, {%4,%5,%6,%7}, {%8,%9}, {%0,%1,%2,%3};\n"
        : "+f"(c[0]), "+f"(c[1]), "+f"(c[2]), "+f"(c[3])
        : "r"(a0), "r"(a1), "r"(a2), "r"(a3), "r"(b0), "r"(b1));
}

__device__ __forceinline__ void ldsm4(uint32_t& r0, uint32_t& r1, uint32_t& r2, uint32_t& r3,
                                      uint32_t addr) {
    asm volatile("ldmatrix.sync.aligned.m8n8.x4.shared.b16 {%0,%1,%2,%3}, [%4];"
                 : "=r"(r0), "=r"(r1), "=r"(r2), "=r"(r3) : "r"(addr));
}

__device__ __forceinline__ void ldsm4t(uint32_t& r0, uint32_t& r1, uint32_t& r2, uint32_t& r3,
                                       uint32_t addr) {
    asm volatile("ldmatrix.sync.aligned.m8n8.x4.trans.shared.b16 {%0,%1,%2,%3}, [%4];"
                 : "=r"(r0), "=r"(r1), "=r"(r2), "=r"(r3) : "r"(addr));
}

__device__ __forceinline__ void cp16(uint32_t dst_smem, const void* src) {
    asm volatile("cp.async.cg.shared.global [%0], [%1], 16;\n" :: "r"(dst_smem), "l"(src));
}
__device__ __forceinline__ void cp_commit() { asm volatile("cp.async.commit_group;\n"); }
__device__ __forceinline__ void cp_wait1() { asm volatile("cp.async.wait_group 1;\n"); }
__device__ __forceinline__ void cp_wait0() { asm volatile("cp.async.wait_group 0;\n"); }

// ---------------------------------------------------------------------------
// Kernel 0: fp32 -> fp16 conversion of X, w_qkv, w_out
// ---------------------------------------------------------------------------
#define NX4  (NB * CDIM * NN / 4)
#define NWQ4 (QKV_M * CDIM / 4)
#define NWO4 (CDIM * CDIM / 4)
#define CVT4 (NX4 + NWQ4 + NWO4)

__global__ __launch_bounds__(256) void cvt_kernel(const float* __restrict__ x,
                                                  const float* __restrict__ wq,
                                                  const float* __restrict__ wo)
{
    int idx = blockIdx.x * 256 + threadIdx.x;
    if (idx >= CVT4) return;
    const float4* src; __half* dst; int j;
    if (idx < NX4)             { src = (const float4*)x;  dst = g_xh;  j = idx; }
    else if (idx < NX4 + NWQ4) { src = (const float4*)wq; dst = g_wqh; j = idx - NX4; }
    else                       { src = (const float4*)wo; dst = g_woh; j = idx - NX4 - NWQ4; }
    float4 v = src[j];
    uint2 hh;
    hh.x = f2h2(v.x, v.y); hh.y = f2h2(v.z, v.w);
    *(uint2*)&dst[4 * j] = hh;
}

// ---------------------------------------------------------------------------
// fp16 MMA GEMM (128x128x32), cp.async 2-stage. 256 thr = 8 warps (4m x 2n).
// ---------------------------------------------------------------------------
#define GBM 128
#define GBN 128
#define GBK 32
#define APH 40
#define BPH 136
#define A_STG (GBM * APH)
#define B_STG (GBK * BPH)
#define KTILES (CDIM / GBK)   // 8

struct GemmAcc { float acc[2][8][4]; };

__device__ __forceinline__ void gemm_issue(uint32_t as_b, uint32_t bs_b, int s,
                                           const __half* __restrict__ Ag,
                                           const __half* __restrict__ Bg,
                                           int m0, int n0, int k0, int tid)
{
    #pragma unroll
    for (int i = 0; i < 2; i++) {
        int slot = i * 256 + tid;
        int row = slot >> 2, c = (slot & 3) * 8;
        cp16(as_b + (uint32_t)(s * A_STG + row * APH + c) * 2,
             Ag + (size_t)(m0 + row) * CDIM + k0 + c);
    }
    #pragma unroll
    for (int i = 0; i < 2; i++) {
        int slot = i * 256 + tid;
        int row = slot >> 4, c = (slot & 15) * 8;
        cp16(bs_b + (uint32_t)(s * B_STG + row * BPH + c) * 2,
             Bg + (size_t)(k0 + row) * NN + n0 + c);
    }
    cp_commit();
}

__device__ __forceinline__ void gemm_core(__half* As, __half* Bs,
                                          const __half* __restrict__ Ag,
                                          const __half* __restrict__ Bg,
                                          int m0, int n0, GemmAcc& R)
{
    const int tid = threadIdx.x;
    const int warp = tid >> 5;
    const int lane = tid & 31;
    const int wm = (warp >> 1) * 32;
    const int wn = (warp & 1) * 64;
    const uint32_t as_b = (uint32_t)__cvta_generic_to_shared(As);
    const uint32_t bs_b = (uint32_t)__cvta_generic_to_shared(Bs);

    #pragma unroll
    for (int mt = 0; mt < 2; mt++)
        #pragma unroll
        for (int nt = 0; nt < 8; nt++)
            #pragma unroll
            for (int r = 0; r < 4; r++) R.acc[mt][nt][r] = 0.f;

    gemm_issue(as_b, bs_b, 0, Ag, Bg, m0, n0, 0, tid);

    #pragma unroll 1
    for (int kt = 0; kt < KTILES; kt++) {
        if (kt < KTILES - 1) {
            gemm_issue(as_b, bs_b, (kt + 1) & 1, Ag, Bg, m0, n0, (kt + 1) * GBK, tid);
            cp_wait1();
        } else {
            cp_wait0();
        }
        __syncthreads();

        const uint32_t a_base = as_b + (uint32_t)((kt & 1) * A_STG) * 2;
        const uint32_t b_base = bs_b + (uint32_t)((kt & 1) * B_STG) * 2;

        #pragma unroll
        for (int ks = 0; ks < 2; ks++) {
            int kk = 16 * ks;
            uint32_t af[2][4];
            #pragma unroll
            for (int mt = 0; mt < 2; mt++) {
                int r = wm + 16 * mt + (lane & 7) + 8 * ((lane >> 3) & 1);
                int c = kk + 8 * ((lane >> 4) & 1);
                ldsm4(af[mt][0], af[mt][1], af[mt][2], af[mt][3],
                      a_base + (uint32_t)(r * APH + c) * 2);
            }
            #pragma unroll
            for (int nb = 0; nb < 4; nb++) {
                int kr = kk + (lane & 7) + 8 * ((lane >> 3) & 1);
                int nc = wn + 16 * nb + 8 * ((lane >> 4) & 1);
                uint32_t b0, b1, b2, b3;
                ldsm4t(b0, b1, b2, b3, b_base + (uint32_t)(kr * BPH + nc) * 2);
                mma_f16(R.acc[0][2 * nb],     af[0][0], af[0][1], af[0][2], af[0][3], b0, b1);
                mma_f16(R.acc[0][2 * nb + 1], af[0][0], af[0][1], af[0][2], af[0][3], b2, b3);
                mma_f16(R.acc[1][2 * nb],     af[1][0], af[1][1], af[1][2], af[1][3], b0, b1);
                mma_f16(R.acc[1][2 * nb + 1], af[1][0], af[1][1], af[1][2], af[1][3], b2, b3);
            }
        }
        __syncthreads();
    }
}

// Kernel 1: QKV projection; writes fp16 [b][h][d][n]; Q scaled by SCALE*log2e.
__global__ __launch_bounds__(256) void qkv_gemm_kernel()
{
    __shared__ __half As[2 * A_STG];
    __shared__ __half Bs[2 * B_STG];
    const int b = blockIdx.z;
    const int m0 = blockIdx.y * GBM;
    const int n0 = blockIdx.x * GBN;

    GemmAcc R;
    gemm_core(As, Bs, g_wqh, g_xh + (size_t)b * CDIM * NN, m0, n0, R);

    const int tid = threadIdx.x;
    const int warp = tid >> 5, lane = tid & 31;
    const int g = lane >> 2, tig = lane & 3;
    const int wm = (warp >> 1) * 32, wn = (warp & 1) * 64;

    #pragma unroll
    for (int mt = 0; mt < 2; mt++) {
        #pragma unroll
        for (int half = 0; half < 2; half++) {
            int o = m0 + wm + 16 * mt + g + 8 * half;
            int grp = o >> 8;
            int hh = (o >> 5) & 7;
            int dd = o & 31;
            __half* dst = (grp == 0) ? g_qh : (grp == 1) ? g_kh : g_vh;
            float sc = (grp == 0) ? QSCALE : 1.0f;
            __half* rowp = dst + ((size_t)(b * NH + hh) * ND + dd) * NN;
            #pragma unroll
            for (int nt = 0; nt < 8; nt++) {
                int n = n0 + wn + 8 * nt + 2 * tig;
                *(uint32_t*)&rowp[n] =
                    f2h2(R.acc[mt][nt][2 * half] * sc, R.acc[mt][nt][2 * half + 1] * sc);
            }
        }
    }
}

// ---------------------------------------------------------------------------
// Kernel 3: output projection + bias, 64x128 tiles for 256-CTA grid.
// 256 thr = 8 warps (2m x 4n), warp tile 32x32.
// ---------------------------------------------------------------------------
#define OBM 64
#define OA_STG (OBM * APH)

__device__ __forceinline__ void out_issue(uint32_t as_b, uint32_t bs_b, int s,
                                          const __half* __restrict__ Ag,
                                          const __half* __restrict__ Bg,
                                          int m0, int n0, int k0, int tid)
{
    // A tile 64x32 halves: 4 chunks/row, 256 total -> 1/thread
    {
        int row = tid >> 2, c = (tid & 3) * 8;
        cp16(as_b + (uint32_t)(s * OA_STG + row * APH + c) * 2,
             Ag + (size_t)(m0 + row) * CDIM + k0 + c);
    }
    // B tile 32x128 halves: 16 chunks/row, 512 total -> 2/thread
    #pragma unroll
    for (int i = 0; i < 2; i++) {
        int slot = i * 256 + tid;
        int row = slot >> 4, c = (slot & 15) * 8;
        cp16(bs_b + (uint32_t)(s * B_STG + row * BPH + c) * 2,
             Bg + (size_t)(k0 + row) * NN + n0 + c);
    }
    cp_commit();
}

__global__ __launch_bounds__(256) void out_gemm_kernel(
    const float* __restrict__ bias,  // [256]
    float* __restrict__ Y)           // [B, 256, 1024]
{
    __shared__ __half As[2 * OA_STG];
    __shared__ __half Bs[2 * B_STG];
    const int b = blockIdx.z;
    const int m0 = blockIdx.y * OBM;
    const int n0 = blockIdx.x * GBN;
    const __half* Ag = g_woh;
    const __half* Bg = g_aoh + (size_t)b * CDIM * NN;

    const int tid = threadIdx.x;
    const int warp = tid >> 5;
    const int lane = tid & 31;
    const int g = lane >> 2, tig = lane & 3;
    const int wm = (warp >> 2) * 32;   // 2 warps in m
    const int wn = (warp & 3) * 32;    // 4 warps in n
    const uint32_t as_b = (uint32_t)__cvta_generic_to_shared(As);
    const uint32_t bs_b = (uint32_t)__cvta_generic_to_shared(Bs);

    float acc[2][4][4];
    #pragma unroll
    for (int mt = 0; mt < 2; mt++)
        #pragma unroll
        for (int nt = 0; nt < 4; nt++)
            #pragma unroll
            for (int r = 0; r < 4; r++) acc[mt][nt][r] = 0.f;

    out_issue(as_b, bs_b, 0, Ag, Bg, m0, n0, 0, tid);

    #pragma unroll 1
    for (int kt = 0; kt < KTILES; kt++) {
        if (kt < KTILES - 1) {
            out_issue(as_b, bs_b, (kt + 1) & 1, Ag, Bg, m0, n0, (kt + 1) * GBK, tid);
            cp_wait1();
        } else {
            cp_wait0();
        }
        __syncthreads();

        const uint32_t a_base = as_b + (uint32_t)((kt & 1) * OA_STG) * 2;
        const uint32_t b_base = bs_b + (uint32_t)((kt & 1) * B_STG) * 2;

        #pragma unroll
        for (int ks = 0; ks < 2; ks++) {
            int kk = 16 * ks;
            uint32_t af[2][4];
            #pragma unroll
            for (int mt = 0; mt < 2; mt++) {
                int r = wm + 16 * mt + (lane & 7) + 8 * ((lane >> 3) & 1);
                int c = kk + 8 * ((lane >> 4) & 1);
                ldsm4(af[mt][0], af[mt][1], af[mt][2], af[mt][3],
                      a_base + (uint32_t)(r * APH + c) * 2);
            }
            #pragma unroll
            for (int nb = 0; nb < 2; nb++) {
                int kr = kk + (lane & 7) + 8 * ((lane >> 3) & 1);
                int nc = wn + 16 * nb + 8 * ((lane >> 4) & 1);
                uint32_t b0, b1, b2, b3;
                ldsm4t(b0, b1, b2, b3, b_base + (uint32_t)(kr * BPH + nc) * 2);
                mma_f16(acc[0][2 * nb],     af[0][0], af[0][1], af[0][2], af[0][3], b0, b1);
                mma_f16(acc[0][2 * nb + 1], af[0][0], af[0][1], af[0][2], af[0][3], b2, b3);
                mma_f16(acc[1][2 * nb],     af[1][0], af[1][1], af[1][2], af[1][3], b0, b1);
                mma_f16(acc[1][2 * nb + 1], af[1][0], af[1][1], af[1][2], af[1][3], b2, b3);
            }
        }
        __syncthreads();
    }

    #pragma unroll
    for (int mt = 0; mt < 2; mt++) {
        #pragma unroll
        for (int half = 0; half < 2; half++) {
            int o = m0 + wm + 16 * mt + g + 8 * half;
            float bv = bias[o];
            float* yrow = Y + ((size_t)b * CDIM + o) * NN;
            #pragma unroll
            for (int nt = 0; nt < 4; nt++) {
                int n = n0 + wn + 8 * nt + 2 * tig;
                yrow[n]     = acc[mt][nt][2 * half]     + bv;
                yrow[n + 1] = acc[mt][nt][2 * half + 1] + bv;
            }
        }
    }
}

// ---------------------------------------------------------------------------
// Kernel 2: fp16 flash attention. No-max softmax via ex2.f16x2 on packed
// accumulator pairs (L2E pre-folded into Q); row sums via constant ones-column
// MMA (fp32 accumulate, consistent with fp16 P). cp.async double-buffered K/V.
// 128 threads (4 warps), Br=64, Bc=64. Static smem 23KB.
// ---------------------------------------------------------------------------
#define BR   64
#define BC   64
#define TPH  72
#define T_STG (ND * TPH)
#define NTILES (NN / BC)   // 16

__device__ __forceinline__ void attn_issue(uint32_t ks_b, uint32_t vs_b, int s,
                                           const __half* __restrict__ Kg,
                                           const __half* __restrict__ Vg,
                                           int j0, int tid)
{
    #pragma unroll
    for (int i = 0; i < 2; i++) {
        int slot = i * 128 + tid;
        int row = slot >> 3, c = (slot & 7) * 8;
        cp16(ks_b + (uint32_t)(s * T_STG + row * TPH + c) * 2,
             Kg + (size_t)row * NN + j0 + c);
        cp16(vs_b + (uint32_t)(s * T_STG + row * TPH + c) * 2,
             Vg + (size_t)row * NN + j0 + c);
    }
    cp_commit();
}

__global__ __launch_bounds__(128) void attn_kernel()
{
    __shared__ __half Qs[T_STG];
    __shared__ __half Ks[2 * T_STG];
    __shared__ __half Vs[2 * T_STG];

    const int b = blockIdx.z;
    const int h = blockIdx.y;
    const int q0 = blockIdx.x * BR;

    const int tid = threadIdx.x;
    const int warp = tid >> 5, lane = tid & 31;
    const int g = lane >> 2, tig = lane & 3;
    // constant B-fragment: ones in column n=0 of an 8-wide block (held by g==0)
    const uint32_t bones = (g == 0) ? 0x3C003C00u : 0u;

    const size_t headBase = (size_t)(b * NH + h) * ND * NN;
    const __half* Qg = g_qh + headBase;
    const __half* Kg = g_kh + headBase;
    const __half* Vg = g_vh + headBase;
    const uint32_t qs_b = (uint32_t)__cvta_generic_to_shared(Qs);
    const uint32_t ks_b = (uint32_t)__cvta_generic_to_shared(Ks);
    const uint32_t vs_b = (uint32_t)__cvta_generic_to_shared(Vs);

    attn_issue(ks_b, vs_b, 0, Kg, Vg, 0, tid);
    #pragma unroll
    for (int i = 0; i < 2; i++) {
        int slot = i * 128 + tid;
        int row = slot >> 3, c = (slot & 7) * 8;
        *(uint4*)&Qs[row * TPH + c] = *(const uint4*)&Qg[(size_t)row * NN + q0 + c];
    }
    __syncthreads();

    uint32_t qf[2][4];
    const int ib = 16 * warp;
    #pragma unroll
    for (int ks = 0; ks < 2; ks++) {
        int dr = 16 * ks + (lane & 7) + 8 * ((lane >> 4) & 1);
        int ic = ib + 8 * ((lane >> 3) & 1);
        ldsm4t(qf[ks][0], qf[ks][1], qf[ks][2], qf[ks][3],
               qs_b + (uint32_t)(dr * TPH + ic) * 2);
    }

    float oacc[4][4];
    #pragma unroll
    for (int dt = 0; dt < 4; dt++)
        #pragma unroll
        for (int r = 0; r < 4; r++) oacc[dt][r] = 0.f;
    float osum[4] = {0.f, 0.f, 0.f, 0.f};   // row sums via ones-MMA

    #pragma unroll 1
    for (int t = 0; t < NTILES; t++) {
        if (t < NTILES - 1) {
            attn_issue(ks_b, vs_b, (t + 1) & 1, Kg, Vg, (t + 1) * BC, tid);
            cp_wait1();
        } else {
            cp_wait0();
        }
        __syncthreads();

        const uint32_t kb = ks_b + (uint32_t)((t & 1) * T_STG) * 2;
        const uint32_t vb = vs_b + (uint32_t)((t & 1) * T_STG) * 2;

        // S*L2E = Q K^T (L2E folded into Q)
        float sacc[8][4];
        #pragma unroll
        for (int nt = 0; nt < 8; nt++)
            #pragma unroll
            for (int r = 0; r < 4; r++) sacc[nt][r] = 0.f;
        #pragma unroll
        for (int ks = 0; ks < 2; ks++) {
            int kk = 16 * ks;
            #pragma unroll
            for (int nb = 0; nb < 4; nb++) {
                int kr = kk + (lane & 7) + 8 * ((lane >> 3) & 1);
                int jc = 16 * nb + 8 * ((lane >> 4) & 1);
                uint32_t b0, b1, b2, b3;
                ldsm4t(b0, b1, b2, b3, kb + (uint32_t)(kr * TPH + jc) * 2);
                mma_f16(sacc[2 * nb],     qf[ks][0], qf[ks][1], qf[ks][2], qf[ks][3], b0, b1);
                mma_f16(sacc[2 * nb + 1], qf[ks][0], qf[ks][1], qf[ks][2], qf[ks][3], b2, b3);
            }
        }

        // p = exp2(sacc) in f16x2, packed directly as PV A-fragments
        uint32_t pa[8][2];
        #pragma unroll
        for (int nt = 0; nt < 8; nt++) {
            pa[nt][0] = ex2h2(f2h2(sacc[nt][0], sacc[nt][1]));
            pa[nt][1] = ex2h2(f2h2(sacc[nt][2], sacc[nt][3]));
        }

        // O += P V ; row sums += P @ ones (constant B-fragment, no loads)
        #pragma unroll
        for (int ks2 = 0; ks2 < 4; ks2++) {
            uint32_t a0 = pa[2 * ks2][0],     a1 = pa[2 * ks2][1];
            uint32_t a2 = pa[2 * ks2 + 1][0], a3 = pa[2 * ks2 + 1][1];
            #pragma unroll
            for (int db = 0; db < 2; db++) {
                int dr = 16 * db + (lane & 7) + 8 * ((lane >> 4) & 1);
                int jc = 16 * ks2 + 8 * ((lane >> 3) & 1);
                uint32_t b0, b1, b2, b3;
                ldsm4(b0, b1, b2, b3, vb + (uint32_t)(dr * TPH + jc) * 2);
                mma_f16(oacc[2 * db],     a0, a1, a2, a3, b0, b1);
                mma_f16(oacc[2 * db + 1], a0, a1, a2, a3, b2, b3);
            }
            mma_f16(osum, a0, a1, a2, a3, bones, bones);
        }
        __syncthreads();
    }

    // Row sums live in column 0 of the sum block (threads tig==0): broadcast.
    float s0 = __shfl_sync(0xffffffffu, osum[0], lane & 28);
    float s1 = __shfl_sync(0xffffffffu, osum[2], lane & 28);
    float inv0 = 1.0f / s0;
    float inv1 = 1.0f / s1;

    int n_row0 = q0 + 16 * warp + g;
    __half* aoB = g_aoh + ((size_t)b * CDIM + h * ND) * NN;
    #pragma unroll
    for (int dt = 0; dt < 4; dt++) {
        int d = 8 * dt + 2 * tig;
        aoB[(size_t)d * NN + n_row0]           = __float2half_rn(oacc[dt][0] * inv0);
        aoB[(size_t)(d + 1) * NN + n_row0]     = __float2half_rn(oacc[dt][1] * inv0);
        aoB[(size_t)d * NN + n_row0 + 8]       = __float2half_rn(oacc[dt][2] * inv1);
        aoB[(size_t)(d + 1) * NN + n_row0 + 8] = __float2half_rn(oacc[dt][3] * inv1);
    }
}

// ---------------------------------------------------------------------------
extern "C" void kernel_launch(void* const* d_in, const int* in_sizes, int n_in,
                              void* d_out, int out_size)
{
    const float* x     = (const float*)d_in[0];
    const float* w_qkv = (const float*)d_in[1];
    const float* w_out = (const float*)d_in[2];
    const float* b_out = (const float*)d_in[3];
    float* y = (float*)d_out;

    cvt_kernel<<<(CVT4 + 255) / 256, 256>>>(x, w_qkv, w_out);
    qkv_gemm_kernel<<<dim3(NN / GBN, QKV_M / GBM, NB), 256>>>();
    attn_kernel<<<dim3(NN / BR, NH, NB), 128>>>();
    out_gemm_kernel<<<dim3(NN / GBN, CDIM / OBM, NB), 256>>>(b_out, y);
}